// round 14
// baseline (speedup 1.0000x reference)
#include <cuda_runtime.h>
#include <cuda_fp16.h>
#include <math.h>
#include <stdint.h>

// ---------------- problem constants ----------------
#define Bb    64
#define Cc    2048
#define LL    196
#define L1    197
#define HID   2048
#define OUTC  256
#define NH    8
#define CH    (Cc / NH)
#define KH    (OUTC / NH)
#define N1    (Bb * L1)     // 12608
#define N2    (Bb * KH)     // 2048
#define KDIM  2048

#define OFF_ZG    0
#define OFF_VAL   (Bb * OUTC)
#define OFF_ATTN  (OFF_VAL + Bb * OUTC * KH)
#define OFF_RAW   (OFF_ATTN + Bb * NH * KH * LL)

// ---------------- device scratch ----------------
__device__ __half  d_X1h[(size_t)N1 * Cc];    // (b, l, c) fp16
__device__ __half  d_Hh[(size_t)N1 * HID];    // H pre-BN fp16
__device__ float   d_Z [(size_t)N1 * OUTC];
__device__ __half  d_Vth[(size_t)N2 * Cc];
__device__ float   d_P4[(size_t)4 * N2 * OUTC];   // GEMM4 split-K partials
__device__ float   d_part_s[128 * HID];
__device__ float   d_part_q[128 * HID];
__device__ __half2 d_hs[HID / 2];             // BN scale, packed pairs
__device__ __half2 d_hb[HID / 2];             // BN shift, packed pairs
__device__ float   d_poolp[Bb * Cc * 7];      // pool partials per l-block
__device__ __half  d_W1p[(size_t)HID * Cc];
__device__ __half  d_W2p[(size_t)OUTC * HID];
__device__ __half  d_W1o[(size_t)HID * Cc];
__device__ __half  d_W2o[(size_t)OUTC * HID];

// ---------------- helpers ----------------
__device__ __forceinline__ uint32_t smem_u32(const void* p) {
    return (uint32_t)__cvta_generic_to_shared(p);
}

__device__ __forceinline__ void cpasync16_s(uint32_t saddr, const void* g, bool pred) {
    int sz = pred ? 16 : 0;
    asm volatile("cp.async.cg.shared.global [%0], [%1], 16, %2;"
                 :: "r"(saddr), "l"(g), "r"(sz));
}

__device__ __forceinline__ void ldsm4(uint32_t* r, uint32_t addr) {
    asm volatile("ldmatrix.sync.aligned.m8n8.x4.shared.b16 {%0,%1,%2,%3}, [%4];"
                 : "=r"(r[0]), "=r"(r[1]), "=r"(r[2]), "=r"(r[3]) : "r"(addr));
}

__device__ __forceinline__ void mma16816(float* d, const uint32_t* a,
                                         uint32_t b0, uint32_t b1) {
    asm volatile(
        "mma.sync.aligned.m16n8k16.row.col.f32.f16.f16.f32 "
        "{%0,%1,%2,%3}, {%4,%5,%6,%7}, {%8,%9}, {%0,%1,%2,%3};"
        : "+f"(d[0]), "+f"(d[1]), "+f"(d[2]), "+f"(d[3])
        : "r"(a[0]), "r"(a[1]), "r"(a[2]), "r"(a[3]), "r"(b0), "r"(b1));
}

__device__ __forceinline__ uint32_t bnrelu2(uint32_t h, __half2 s, __half2 o) {
    __half2 v = *reinterpret_cast<__half2*>(&h);
    v = __hmax2(__hfma2(v, s, o), __half2half2(__ushort_as_half(0)));
    return *reinterpret_cast<uint32_t*>(&v);
}

// ================= fp16 mma.sync GEMM (R12-proven: BK=32, 4-slot, 2-ahead) ====
template <int ROWS, int COLS, bool HOUT, bool BNRELU, bool STATS, int SPLIT>
__global__ __launch_bounds__(256, 2)
void gemm_h(const __half* __restrict__ A, const __half* __restrict__ W,
            void* __restrict__ Cout, int R, int Cols,
            const __half2* __restrict__ hs, const __half2* __restrict__ hb,
            float* __restrict__ part_s, float* __restrict__ part_q)
{
    constexpr int WN  = COLS / 64;
    constexpr int WM  = 8 / WN;
    constexpr int MI  = ROWS / (16 * WM);
    constexpr int A_STG = ROWS * 80;
    constexpr int B_STG = COLS * 80;
    constexpr int B_OFF = 4 * A_STG;
    constexpr int NIT = KDIM / (32 * SPLIT);

    extern __shared__ char sm[];
    const uint32_t sbase = smem_u32(sm);
    const int tid  = threadIdx.x;
    const int warp = tid >> 5, lane = tid & 31;
    const int tg = lane & 3;
    const int wm = warp / WN, wn = warp % WN;
    const int row0 = blockIdx.y * ROWS;
    const int col0 = blockIdx.x * COLS;
    const int kOff = (SPLIT > 1) ? (int)blockIdx.z * (KDIM / SPLIT) : 0;

    float acc[MI][8][4] = {};

    auto loadStage = [&](int j) {
        const int st = j & 3;
        const uint32_t aB = sbase + st * A_STG;
        const uint32_t bB = sbase + B_OFF + st * B_STG;
        const __half* Aj = A + (size_t)row0 * KDIM + kOff + j * 32;
        const __half* Wj = W + (size_t)col0 * KDIM + kOff + j * 32;
        #pragma unroll
        for (int i = 0; i < ROWS / 64; i++) {
            int task = tid + i * 256;
            int r = task >> 2, ch = task & 3;
            bool p = (row0 + r) < R;
            cpasync16_s(aB + r * 80 + ch * 16,
                        Aj + (size_t)(p ? r : 0) * KDIM + ch * 8, p);
        }
        #pragma unroll
        for (int i = 0; i < COLS / 64; i++) {
            int task = tid + i * 256;
            int r = task >> 2, ch = task & 3;
            cpasync16_s(bB + r * 80 + ch * 16,
                        Wj + (size_t)r * KDIM + ch * 8, true);
        }
        asm volatile("cp.async.commit_group;");
    };

    loadStage(0);
    loadStage(1);

    for (int it = 0; it < NIT; it++) {
        int j = it + 2;
        if (j < NIT) {
            loadStage(j);                              // issue loads FIRST
            asm volatile("cp.async.wait_group 2;");    // then block on stage `it`
        } else {
            asm volatile("cp.async.wait_group 0;");
        }
        __syncthreads();

        const int st = it & 3;
        const uint32_t aB = sbase + st * A_STG;
        const uint32_t bB = sbase + B_OFF + st * B_STG;

        #pragma unroll
        for (int kt = 0; kt < 2; kt++) {
            uint32_t af[MI][4], bf[4][4];
            #pragma unroll
            for (int mi = 0; mi < MI; mi++) {
                int rowb = wm * (MI * 16) + mi * 16 + (lane & 15);
                uint32_t addr = aB + rowb * 80 + kt * 32 + ((lane >> 4) << 4);
                ldsm4(af[mi], addr);
            }
            if (BNRELU) {
                const int pidx = kOff / 2 + it * 16 + kt * 8 + tg;
                __half2 s0 = hs[pidx],     o0 = hb[pidx];
                __half2 s1 = hs[pidx + 4], o1 = hb[pidx + 4];
                #pragma unroll
                for (int mi = 0; mi < MI; mi++) {
                    af[mi][0] = bnrelu2(af[mi][0], s0, o0);
                    af[mi][1] = bnrelu2(af[mi][1], s0, o0);
                    af[mi][2] = bnrelu2(af[mi][2], s1, o1);
                    af[mi][3] = bnrelu2(af[mi][3], s1, o1);
                }
            }
            #pragma unroll
            for (int jp = 0; jp < 4; jp++) {
                int rown = wn * 64 + jp * 16 + (lane & 7) + ((lane >> 4) << 3);
                uint32_t addr = bB + rown * 80 + kt * 32 + (((lane >> 3) & 1) << 4);
                ldsm4(bf[jp], addr);
            }
            #pragma unroll
            for (int mi = 0; mi < MI; mi++)
                #pragma unroll
                for (int jp = 0; jp < 4; jp++) {
                    mma16816(acc[mi][jp * 2],     af[mi], bf[jp][0], bf[jp][1]);
                    mma16816(acc[mi][jp * 2 + 1], af[mi], bf[jp][2], bf[jp][3]);
                }
        }
    }

    if (STATS) {
        float sl[8][2] = {}, ql[8][2] = {};
        #pragma unroll
        for (int nj = 0; nj < 8; nj++)
            #pragma unroll
            for (int mi = 0; mi < MI; mi++) {
                float v0 = acc[mi][nj][0], v1 = acc[mi][nj][1];
                float v2 = acc[mi][nj][2], v3 = acc[mi][nj][3];
                sl[nj][0] += v0 + v2;  ql[nj][0] += v0 * v0 + v2 * v2;
                sl[nj][1] += v1 + v3;  ql[nj][1] += v1 * v1 + v3 * v3;
            }
        #pragma unroll
        for (int off = 4; off < 32; off <<= 1)
            #pragma unroll
            for (int nj = 0; nj < 8; nj++) {
                sl[nj][0] += __shfl_xor_sync(~0u, sl[nj][0], off);
                sl[nj][1] += __shfl_xor_sync(~0u, sl[nj][1], off);
                ql[nj][0] += __shfl_xor_sync(~0u, ql[nj][0], off);
                ql[nj][1] += __shfl_xor_sync(~0u, ql[nj][1], off);
            }
        __syncthreads();
        float* sred = reinterpret_cast<float*>(sm);
        if (lane < 4) {
            #pragma unroll
            for (int nj = 0; nj < 8; nj++) {
                int col = wn * 64 + nj * 8 + lane * 2;
                sred[wm * COLS + col]     = sl[nj][0];
                sred[wm * COLS + col + 1] = sl[nj][1];
                sred[WM * COLS + wm * COLS + col]     = ql[nj][0];
                sred[WM * COLS + wm * COLS + col + 1] = ql[nj][1];
            }
        }
        __syncthreads();
        if (tid < COLS) {
            float s = 0.f, q = 0.f;
            #pragma unroll
            for (int w = 0; w < WM; w++) {
                s += sred[w * COLS + tid];
                q += sred[WM * COLS + w * COLS + tid];
            }
            part_s[(size_t)blockIdx.y * Cols + col0 + tid] = s;
            part_q[(size_t)blockIdx.y * Cols + col0 + tid] = q;
        }
    }

    const size_t splitOff = (SPLIT > 1) ? (size_t)blockIdx.z * R * Cols : 0;
    #pragma unroll
    for (int mi = 0; mi < MI; mi++) {
        int rbase = row0 + wm * (MI * 16) + mi * 16 + (lane >> 2);
        #pragma unroll
        for (int nj = 0; nj < 8; nj++) {
            int c = col0 + wn * 64 + nj * 8 + (lane & 3) * 2;
            if (HOUT) {
                __half* Ch = (__half*)Cout;
                if (rbase < R)
                    *reinterpret_cast<__half2*>(&Ch[(size_t)rbase * Cols + c]) =
                        __floats2half2_rn(acc[mi][nj][0], acc[mi][nj][1]);
                if (rbase + 8 < R)
                    *reinterpret_cast<__half2*>(&Ch[(size_t)(rbase + 8) * Cols + c]) =
                        __floats2half2_rn(acc[mi][nj][2], acc[mi][nj][3]);
            } else {
                float* Cf = (float*)Cout + splitOff;
                if (rbase < R)
                    *reinterpret_cast<float2*>(&Cf[(size_t)rbase * Cols + c]) =
                        make_float2(acc[mi][nj][0], acc[mi][nj][1]);
                if (rbase + 8 < R)
                    *reinterpret_cast<float2*>(&Cf[(size_t)(rbase + 8) * Cols + c]) =
                        make_float2(acc[mi][nj][2], acc[mi][nj][3]);
            }
        }
    }
}

// ---------------- transpose (b,c,l)->(b,1+l,c) fp16 + pool partials ----------------
__global__ void transpose_kernel(const float* __restrict__ x) {
    __shared__ float t[32][33];
    __shared__ float ps[8][32];
    int b  = blockIdx.z;
    int c0 = blockIdx.y * 32;
    int l0 = blockIdx.x * 32;
    int tx = threadIdx.x, ty = threadIdx.y;
    #pragma unroll
    for (int i = 0; i < 32; i += 8) {
        int c = c0 + ty + i, l = l0 + tx;
        t[ty + i][tx] = (l < LL) ? x[((size_t)b * Cc + c) * LL + l] : 0.f;
    }
    __syncthreads();
    #pragma unroll
    for (int i = 0; i < 32; i += 8) {
        int l = l0 + ty + i, c = c0 + tx;
        if (l < LL)
            d_X1h[((size_t)b * L1 + 1 + l) * Cc + c] = __float2half_rn(t[tx][ty + i]);
    }
    float p = t[tx][ty * 4] + t[tx][ty * 4 + 1] + t[tx][ty * 4 + 2] + t[tx][ty * 4 + 3];
    ps[ty][tx] = p;
    __syncthreads();
    if (ty == 0) {
        float s = 0.f;
        #pragma unroll
        for (int i = 0; i < 8; i++) s += ps[i][tx];
        d_poolp[((size_t)b * Cc + c0 + tx) * 7 + blockIdx.x] = s;
    }
}

// ---------------- pool finalize: X1 row 0 ----------------
__global__ void pool_final() {
    int idx = blockIdx.x * 256 + threadIdx.x;       // < Bb*Cc
    int b = idx >> 11, c = idx & (Cc - 1);
    float s = 0.f;
    #pragma unroll
    for (int j = 0; j < 7; j++) s += d_poolp[(size_t)idx * 7 + j];
    d_X1h[((size_t)b * L1) * Cc + c] = __float2half_rn(s * (1.f / (float)LL));
}

// ---------------- fused fp32 -> fp16 weight copies ----------------
#define WCP_N0  (HID * Cc / 4)
#define WCP_N1  (OUTC * HID / 4)
#define WCP_TOT (2 * WCP_N0 + 2 * WCP_N1)
__global__ void half_copy4(const float* __restrict__ s0, __half* __restrict__ d0,
                           const float* __restrict__ s1, __half* __restrict__ d1,
                           const float* __restrict__ s2, __half* __restrict__ d2,
                           const float* __restrict__ s3, __half* __restrict__ d3) {
    int i = blockIdx.x * 256 + threadIdx.x;
    const float* src; __half* dst; int off;
    if (i < WCP_N0)                       { src = s0; dst = d0; off = i; }
    else if (i < WCP_N0 + WCP_N1)         { src = s1; dst = d1; off = i - WCP_N0; }
    else if (i < 2 * WCP_N0 + WCP_N1)     { src = s2; dst = d2; off = i - WCP_N0 - WCP_N1; }
    else if (i < WCP_TOT)                 { src = s3; dst = d3; off = i - 2 * WCP_N0 - WCP_N1; }
    else return;
    float4 v = reinterpret_cast<const float4*>(src)[off];
    reinterpret_cast<__half2*>(dst)[off * 2    ] = __floats2half2_rn(v.x, v.y);
    reinterpret_cast<__half2*>(dst)[off * 2 + 1] = __floats2half2_rn(v.z, v.w);
}

// ---------------- BN finalize ----------------
__global__ void bn_final(const float* __restrict__ g, const float* __restrict__ bta,
                         float invN, int nch) {
    int i = blockIdx.x * 256 + threadIdx.x;         // < HID/2
    int o0 = 2 * i, o1 = 2 * i + 1;
    float s0 = 0.f, q0 = 0.f, s1 = 0.f, q1 = 0.f;
    for (int ch = 0; ch < nch; ch++) {
        s0 += d_part_s[(size_t)ch * HID + o0]; q0 += d_part_q[(size_t)ch * HID + o0];
        s1 += d_part_s[(size_t)ch * HID + o1]; q1 += d_part_q[(size_t)ch * HID + o1];
    }
    float mu0 = s0 * invN, var0 = q0 * invN - mu0 * mu0;
    float mu1 = s1 * invN, var1 = q1 * invN - mu1 * mu1;
    float sc0 = g[o0] * rsqrtf(var0 + 1e-5f);
    float sc1 = g[o1] * rsqrtf(var1 + 1e-5f);
    d_hs[i] = __floats2half2_rn(sc0, sc1);
    d_hb[i] = __floats2half2_rn(bta[o0] - mu0 * sc0, bta[o1] - mu1 * sc1);
}

// ---------------- fused z_g + L2 norm + softmax (one block per batch) --------
__global__ __launch_bounds__(256)
void zns_kernel(float* __restrict__ out) {
    __shared__ float nrm[LL];
    const int b = blockIdx.x;
    const int tid = threadIdx.x;
    const int warp = tid >> 5, lane = tid & 31;

    // z_g: row l=0 of Z
    out[OFF_ZG + b * OUTC + tid] = d_Z[((size_t)b * L1) * OUTC + tid];

    // Phase A: per-position L2 norm over 256 channels (warp per l)
    for (int l = warp; l < LL; l += 8) {
        const float* zr = d_Z + ((size_t)b * L1 + 1 + l) * OUTC;
        float s = 0.f;
        #pragma unroll
        for (int i = 0; i < 8; i++) {
            float v = zr[lane + i * 32];
            s += v * v;
        }
        #pragma unroll
        for (int o = 16; o; o >>= 1) s += __shfl_down_sync(~0u, s, o);
        if (lane == 0) nrm[l] = sqrtf(s);
    }
    __syncthreads();

    // Phase B: softmax over l per channel j (warp per j)
    for (int j = warp; j < OUTC; j += 8) {
        float v[7];
        float mx = -INFINITY;
        #pragma unroll
        for (int i = 0; i < 7; i++) {
            int l = lane + i * 32;
            if (l < LL) {
                v[i] = d_Z[((size_t)b * L1 + 1 + l) * OUTC + j] / fmaxf(nrm[l], 1e-12f);
                mx = fmaxf(mx, v[i]);
            } else v[i] = -INFINITY;
        }
        #pragma unroll
        for (int o = 16; o; o >>= 1) mx = fmaxf(mx, __shfl_xor_sync(~0u, mx, o));
        float s = 0.f;
        #pragma unroll
        for (int i = 0; i < 7; i++) { v[i] = expf(v[i] - mx); s += v[i]; }
        #pragma unroll
        for (int o = 16; o; o >>= 1) s += __shfl_xor_sync(~0u, s, o);
        float inv = 1.f / s;
        #pragma unroll
        for (int i = 0; i < 7; i++) {
            int l = lane + i * 32;
            if (l < LL) {
                float r = v[i] * inv;
                size_t idx = ((size_t)b * OUTC + j) * LL + l;
                out[OFF_ATTN + idx] = r;
                out[OFF_RAW  + idx] = r;
            }
        }
    }
}

// ---------------- attention-value einsum (reads fp16 X1h) -> fp16 Vt ----------------
__global__ __launch_bounds__(256)
void attnval_kernel(const float* __restrict__ out) {
    const float* attn = out + OFF_ATTN;
    int h = blockIdx.x, b = blockIdx.y;
    __shared__ __half xs2[32][256];
    __shared__ float  as2[32][36];
    int tid = threadIdx.x;
    float acc[KH] = {};

    for (int l0 = 0; l0 < LL; l0 += 32) {
        int lmax = min(32, LL - l0);
        #pragma unroll
        for (int i = 0; i < 4; i++) {
            int task = tid + i * 256;
            int row = task >> 5, t = task & 31;
            if (l0 + row < LL) {
                const uint4* src = reinterpret_cast<const uint4*>(
                    d_X1h + ((size_t)b * L1 + 1 + l0 + row) * Cc + h * CH) + t;
                *(reinterpret_cast<uint4*>(&xs2[row][0]) + t) = *src;
            }
        }
        #pragma unroll
        for (int i = 0; i < 4; i++) {
            int k   = (tid >> 5) + i * 8;
            int col = tid & 31;
            float v = 0.f;
            if (l0 + col < LL)
                v = attn[(((size_t)b * NH + h) * KH + k) * LL + l0 + col];
            as2[col][k] = v;
        }
        __syncthreads();
        for (int l = 0; l < lmax; l++) {
            float xv = __half2float(xs2[l][tid]);
            #pragma unroll
            for (int k4 = 0; k4 < KH / 4; k4++) {
                float4 w = *reinterpret_cast<const float4*>(&as2[l][k4 * 4]);
                acc[k4 * 4 + 0] = fmaf(xv, w.x, acc[k4 * 4 + 0]);
                acc[k4 * 4 + 1] = fmaf(xv, w.y, acc[k4 * 4 + 1]);
                acc[k4 * 4 + 2] = fmaf(xv, w.z, acc[k4 * 4 + 2]);
                acc[k4 * 4 + 3] = fmaf(xv, w.w, acc[k4 * 4 + 3]);
            }
        }
        __syncthreads();
    }
    #pragma unroll
    for (int k = 0; k < KH; k++)
        d_Vth[((size_t)b * KH + k) * Cc + h * CH + tid] = __float2half_rn(acc[k]);
}

// ---------------- final permute + split-K reduce ----------------
__global__ void permute_kernel(float* __restrict__ out) {
    int idx = blockIdx.x * 256 + threadIdx.x;
    int b = idx >> 13;
    int rem = idx & 8191;
    int j = rem >> 5;
    int k = rem & 31;
    size_t src = ((size_t)b * KH + k) * OUTC + j;
    float s = 0.f;
    #pragma unroll
    for (int z = 0; z < 4; z++) s += d_P4[(size_t)z * N2 * OUTC + src];
    out[OFF_VAL + idx] = s;
}

// ---------------- launch ----------------
extern "C" void kernel_launch(void* const* d_in, const int* in_sizes, int n_in,
                              void* d_out, int out_size) {
    const float* x    = (const float*)d_in[0];
    const float* w1_p = (const float*)d_in[1];
    const float* g_p  = (const float*)d_in[2];
    const float* b_p  = (const float*)d_in[3];
    const float* w2_p = (const float*)d_in[4];
    const float* w1_o = (const float*)d_in[5];
    const float* g_o  = (const float*)d_in[6];
    const float* b_o  = (const float*)d_in[7];
    const float* w2_o = (const float*)d_in[8];
    float* out = (float*)d_out;

    float *pZ, *pP4, *pPs, *pPq;
    __half *pX1h, *pHh, *pVth, *pW1p, *pW2p, *pW1o, *pW2o;
    __half2 *pHs, *pHb;
    cudaGetSymbolAddress((void**)&pX1h, d_X1h);
    cudaGetSymbolAddress((void**)&pHh,  d_Hh);
    cudaGetSymbolAddress((void**)&pZ,   d_Z);
    cudaGetSymbolAddress((void**)&pVth, d_Vth);
    cudaGetSymbolAddress((void**)&pP4,  d_P4);
    cudaGetSymbolAddress((void**)&pPs,  d_part_s);
    cudaGetSymbolAddress((void**)&pPq,  d_part_q);
    cudaGetSymbolAddress((void**)&pHs,  d_hs);
    cudaGetSymbolAddress((void**)&pHb,  d_hb);
    cudaGetSymbolAddress((void**)&pW1p, d_W1p);
    cudaGetSymbolAddress((void**)&pW2p, d_W2p);
    cudaGetSymbolAddress((void**)&pW1o, d_W1o);
    cudaGetSymbolAddress((void**)&pW2o, d_W2o);

    auto gemm1  = gemm_h<128, 128, true,  false, true,  1>;  // GEMM1/3: fp16 H + stats
    auto gemm2  = gemm_h<128, 128, false, true,  false, 1>;  // GEMM2: BN+ReLU fused A
    auto gemm4  = gemm_h<64,  128, false, true,  false, 4>;  // GEMM4: BN+ReLU, split-K4
    constexpr int SM_128 = 4 * (128 * 80 + 128 * 80);   // 81920
    constexpr int SM_64  = 4 * (64  * 80 + 128 * 80);   // 61440
    cudaFuncSetAttribute(gemm1, cudaFuncAttributeMaxDynamicSharedMemorySize, SM_128);
    cudaFuncSetAttribute(gemm2, cudaFuncAttributeMaxDynamicSharedMemorySize, SM_128);
    cudaFuncSetAttribute(gemm4, cudaFuncAttributeMaxDynamicSharedMemorySize, SM_64);

    // weights -> fp16 (single fused launch)
    half_copy4<<<(WCP_TOT + 255) / 256, 256>>>(w1_p, pW1p, w2_p, pW2p,
                                               w1_o, pW1o, w2_o, pW2o);

    // 0) transpose + pool partials, then pool finalize (X1 row 0)
    transpose_kernel<<<dim3(7, Cc / 32, Bb), dim3(32, 8)>>>(x);
    pool_final<<<(Bb * Cc) / 256, 256>>>();

    // 1) H = X1 @ w1_p^T (12608 x 2048 x 2048), fp16 out + fused BN stats
    gemm1<<<dim3(HID / 128, (N1 + 127) / 128), 256, SM_128>>>(
        pX1h, pW1p, pHh, N1, HID, nullptr, nullptr, pPs, pPq);

    // 2) BN finalize (packed half2 scale/shift)
    bn_final<<<HID / 512, 256>>>(g_p, b_p, 1.f / (float)N1, (N1 + 127) / 128);

    // 3) Z = relu(bn(H)) @ w2_p^T, BN+ReLU fused into A fragments
    gemm2<<<dim3(OUTC / 128, (N1 + 127) / 128), 256, SM_128>>>(
        pHh, pW2p, pZ, N1, OUTC, pHs, pHb, nullptr, nullptr);

    // 4) fused z_g + norms + softmax (one block per batch)
    zns_kernel<<<Bb, 256>>>(out);

    // 5) attention value (fp16 X1h input) -> fp16 Vt
    attnval_kernel<<<dim3(NH, Bb), 256>>>(out);

    // 6) H = Vt @ w1_o^T (2048 x 2048 x 2048), fp16 out + fused BN stats
    gemm1<<<dim3(HID / 128, N2 / 128), 256, SM_128>>>(
        pVth, pW1o, pHh, N2, HID, nullptr, nullptr, pPs, pPq);

    // 7) BN finalize 2
    bn_final<<<HID / 512, 256>>>(g_o, b_o, 1.f / (float)N2, N2 / 128);

    // 8) C4 partials = relu(bn(H)) @ w2_o^T, split-K x4 -> 256 CTAs
    gemm4<<<dim3(OUTC / 128, N2 / 64, 4), 256, SM_64>>>(
        pHh, pW2o, pP4, N2, OUTC, pHs, pHb, nullptr, nullptr);

    // 9) permute + split-K reduce to obj_val layout
    permute_kernel<<<(Bb * OUTC * KH) / 256, 256>>>(out);
}

// round 15
// speedup vs baseline: 1.0569x; 1.0569x over previous
#include <cuda_runtime.h>
#include <cuda_fp16.h>
#include <math.h>
#include <stdint.h>

// ---------------- problem constants ----------------
#define Bb    64
#define Cc    2048
#define LL    196
#define L1    197
#define HID   2048
#define OUTC  256
#define NH    8
#define CH    (Cc / NH)
#define KH    (OUTC / NH)
#define N1    (Bb * L1)     // 12608
#define N2    (Bb * KH)     // 2048
#define KDIM  2048
#define ZPL   ((size_t)N1 * OUTC)   // one Z partial plane

#define OFF_ZG    0
#define OFF_VAL   (Bb * OUTC)
#define OFF_ATTN  (OFF_VAL + Bb * OUTC * KH)
#define OFF_RAW   (OFF_ATTN + Bb * NH * KH * LL)

// ---------------- device scratch ----------------
__device__ __half  d_X1h[(size_t)N1 * Cc];    // (b, l, c) fp16
__device__ __half  d_Hh[(size_t)N1 * HID];    // H pre-BN fp16
__device__ float   d_ZP[2 * ZPL];             // GEMM2 split-K partial planes
__device__ __half  d_Vth[(size_t)N2 * Cc];
__device__ float   d_P4[(size_t)4 * N2 * OUTC];   // GEMM4 split-K partials
__device__ float   d_nrm[Bb * LL];
__device__ float   d_part_s[128 * HID];
__device__ float   d_part_q[128 * HID];
__device__ __half2 d_hs[HID / 2];             // BN scale, packed pairs
__device__ __half2 d_hb[HID / 2];             // BN shift, packed pairs
__device__ float   d_poolp[Bb * Cc * 7];      // pool partials per l-block
__device__ __half  d_W1p[(size_t)HID * Cc];
__device__ __half  d_W2p[(size_t)OUTC * HID];
__device__ __half  d_W1o[(size_t)HID * Cc];
__device__ __half  d_W2o[(size_t)OUTC * HID];

// ---------------- helpers ----------------
__device__ __forceinline__ uint32_t smem_u32(const void* p) {
    return (uint32_t)__cvta_generic_to_shared(p);
}

__device__ __forceinline__ void cpasync16_s(uint32_t saddr, const void* g, bool pred) {
    int sz = pred ? 16 : 0;
    asm volatile("cp.async.cg.shared.global [%0], [%1], 16, %2;"
                 :: "r"(saddr), "l"(g), "r"(sz));
}

__device__ __forceinline__ void ldsm4(uint32_t* r, uint32_t addr) {
    asm volatile("ldmatrix.sync.aligned.m8n8.x4.shared.b16 {%0,%1,%2,%3}, [%4];"
                 : "=r"(r[0]), "=r"(r[1]), "=r"(r[2]), "=r"(r[3]) : "r"(addr));
}

__device__ __forceinline__ void mma16816(float* d, const uint32_t* a,
                                         uint32_t b0, uint32_t b1) {
    asm volatile(
        "mma.sync.aligned.m16n8k16.row.col.f32.f16.f16.f32 "
        "{%0,%1,%2,%3}, {%4,%5,%6,%7}, {%8,%9}, {%0,%1,%2,%3};"
        : "+f"(d[0]), "+f"(d[1]), "+f"(d[2]), "+f"(d[3])
        : "r"(a[0]), "r"(a[1]), "r"(a[2]), "r"(a[3]), "r"(b0), "r"(b1));
}

__device__ __forceinline__ uint32_t bnrelu2(uint32_t h, __half2 s, __half2 o) {
    __half2 v = *reinterpret_cast<__half2*>(&h);
    v = __hmax2(__hfma2(v, s, o), __half2half2(__ushort_as_half(0)));
    return *reinterpret_cast<uint32_t*>(&v);
}

// ================= fp16 mma.sync GEMM (R12-proven: BK=32, 4-slot, 2-ahead) ====
template <int ROWS, int COLS, bool HOUT, bool BNRELU, bool STATS, int SPLIT>
__global__ __launch_bounds__(256, 2)
void gemm_h(const __half* __restrict__ A, const __half* __restrict__ W,
            void* __restrict__ Cout, int R, int Cols,
            const __half2* __restrict__ hs, const __half2* __restrict__ hb,
            float* __restrict__ part_s, float* __restrict__ part_q)
{
    constexpr int WN  = COLS / 64;
    constexpr int WM  = 8 / WN;
    constexpr int MI  = ROWS / (16 * WM);
    constexpr int A_STG = ROWS * 80;
    constexpr int B_STG = COLS * 80;
    constexpr int B_OFF = 4 * A_STG;
    constexpr int NIT = KDIM / (32 * SPLIT);

    extern __shared__ char sm[];
    const uint32_t sbase = smem_u32(sm);
    const int tid  = threadIdx.x;
    const int warp = tid >> 5, lane = tid & 31;
    const int tg = lane & 3;
    const int wm = warp / WN, wn = warp % WN;
    const int row0 = blockIdx.y * ROWS;
    const int col0 = blockIdx.x * COLS;
    const int kOff = (SPLIT > 1) ? (int)blockIdx.z * (KDIM / SPLIT) : 0;

    float acc[MI][8][4] = {};

    auto loadStage = [&](int j) {
        const int st = j & 3;
        const uint32_t aB = sbase + st * A_STG;
        const uint32_t bB = sbase + B_OFF + st * B_STG;
        const __half* Aj = A + (size_t)row0 * KDIM + kOff + j * 32;
        const __half* Wj = W + (size_t)col0 * KDIM + kOff + j * 32;
        #pragma unroll
        for (int i = 0; i < ROWS / 64; i++) {
            int task = tid + i * 256;
            int r = task >> 2, ch = task & 3;
            bool p = (row0 + r) < R;
            cpasync16_s(aB + r * 80 + ch * 16,
                        Aj + (size_t)(p ? r : 0) * KDIM + ch * 8, p);
        }
        #pragma unroll
        for (int i = 0; i < COLS / 64; i++) {
            int task = tid + i * 256;
            int r = task >> 2, ch = task & 3;
            cpasync16_s(bB + r * 80 + ch * 16,
                        Wj + (size_t)r * KDIM + ch * 8, true);
        }
        asm volatile("cp.async.commit_group;");
    };

    loadStage(0);
    loadStage(1);

    for (int it = 0; it < NIT; it++) {
        int j = it + 2;
        if (j < NIT) {
            loadStage(j);                              // issue loads FIRST
            asm volatile("cp.async.wait_group 2;");    // then block on stage `it`
        } else {
            asm volatile("cp.async.wait_group 0;");
        }
        __syncthreads();

        const int st = it & 3;
        const uint32_t aB = sbase + st * A_STG;
        const uint32_t bB = sbase + B_OFF + st * B_STG;

        #pragma unroll
        for (int kt = 0; kt < 2; kt++) {
            uint32_t af[MI][4], bf[4][4];
            #pragma unroll
            for (int mi = 0; mi < MI; mi++) {
                int rowb = wm * (MI * 16) + mi * 16 + (lane & 15);
                uint32_t addr = aB + rowb * 80 + kt * 32 + ((lane >> 4) << 4);
                ldsm4(af[mi], addr);
            }
            if (BNRELU) {
                const int pidx = kOff / 2 + it * 16 + kt * 8 + tg;
                __half2 s0 = hs[pidx],     o0 = hb[pidx];
                __half2 s1 = hs[pidx + 4], o1 = hb[pidx + 4];
                #pragma unroll
                for (int mi = 0; mi < MI; mi++) {
                    af[mi][0] = bnrelu2(af[mi][0], s0, o0);
                    af[mi][1] = bnrelu2(af[mi][1], s0, o0);
                    af[mi][2] = bnrelu2(af[mi][2], s1, o1);
                    af[mi][3] = bnrelu2(af[mi][3], s1, o1);
                }
            }
            #pragma unroll
            for (int jp = 0; jp < 4; jp++) {
                int rown = wn * 64 + jp * 16 + (lane & 7) + ((lane >> 4) << 3);
                uint32_t addr = bB + rown * 80 + kt * 32 + (((lane >> 3) & 1) << 4);
                ldsm4(bf[jp], addr);
            }
            #pragma unroll
            for (int mi = 0; mi < MI; mi++)
                #pragma unroll
                for (int jp = 0; jp < 4; jp++) {
                    mma16816(acc[mi][jp * 2],     af[mi], bf[jp][0], bf[jp][1]);
                    mma16816(acc[mi][jp * 2 + 1], af[mi], bf[jp][2], bf[jp][3]);
                }
        }
    }

    if (STATS) {
        float sl[8][2] = {}, ql[8][2] = {};
        #pragma unroll
        for (int nj = 0; nj < 8; nj++)
            #pragma unroll
            for (int mi = 0; mi < MI; mi++) {
                float v0 = acc[mi][nj][0], v1 = acc[mi][nj][1];
                float v2 = acc[mi][nj][2], v3 = acc[mi][nj][3];
                sl[nj][0] += v0 + v2;  ql[nj][0] += v0 * v0 + v2 * v2;
                sl[nj][1] += v1 + v3;  ql[nj][1] += v1 * v1 + v3 * v3;
            }
        #pragma unroll
        for (int off = 4; off < 32; off <<= 1)
            #pragma unroll
            for (int nj = 0; nj < 8; nj++) {
                sl[nj][0] += __shfl_xor_sync(~0u, sl[nj][0], off);
                sl[nj][1] += __shfl_xor_sync(~0u, sl[nj][1], off);
                ql[nj][0] += __shfl_xor_sync(~0u, ql[nj][0], off);
                ql[nj][1] += __shfl_xor_sync(~0u, ql[nj][1], off);
            }
        __syncthreads();
        float* sred = reinterpret_cast<float*>(sm);
        if (lane < 4) {
            #pragma unroll
            for (int nj = 0; nj < 8; nj++) {
                int col = wn * 64 + nj * 8 + lane * 2;
                sred[wm * COLS + col]     = sl[nj][0];
                sred[wm * COLS + col + 1] = sl[nj][1];
                sred[WM * COLS + wm * COLS + col]     = ql[nj][0];
                sred[WM * COLS + wm * COLS + col + 1] = ql[nj][1];
            }
        }
        __syncthreads();
        if (tid < COLS) {
            float s = 0.f, q = 0.f;
            #pragma unroll
            for (int w = 0; w < WM; w++) {
                s += sred[w * COLS + tid];
                q += sred[WM * COLS + w * COLS + tid];
            }
            part_s[(size_t)blockIdx.y * Cols + col0 + tid] = s;
            part_q[(size_t)blockIdx.y * Cols + col0 + tid] = q;
        }
    }

    const size_t splitOff = (SPLIT > 1) ? (size_t)blockIdx.z * R * Cols : 0;
    #pragma unroll
    for (int mi = 0; mi < MI; mi++) {
        int rbase = row0 + wm * (MI * 16) + mi * 16 + (lane >> 2);
        #pragma unroll
        for (int nj = 0; nj < 8; nj++) {
            int c = col0 + wn * 64 + nj * 8 + (lane & 3) * 2;
            if (HOUT) {
                __half* Ch = (__half*)Cout;
                if (rbase < R)
                    *reinterpret_cast<__half2*>(&Ch[(size_t)rbase * Cols + c]) =
                        __floats2half2_rn(acc[mi][nj][0], acc[mi][nj][1]);
                if (rbase + 8 < R)
                    *reinterpret_cast<__half2*>(&Ch[(size_t)(rbase + 8) * Cols + c]) =
                        __floats2half2_rn(acc[mi][nj][2], acc[mi][nj][3]);
            } else {
                float* Cf = (float*)Cout + splitOff;
                if (rbase < R)
                    *reinterpret_cast<float2*>(&Cf[(size_t)rbase * Cols + c]) =
                        make_float2(acc[mi][nj][0], acc[mi][nj][1]);
                if (rbase + 8 < R)
                    *reinterpret_cast<float2*>(&Cf[(size_t)(rbase + 8) * Cols + c]) =
                        make_float2(acc[mi][nj][2], acc[mi][nj][3]);
            }
        }
    }
}

// ---------------- transpose (b,c,l)->(b,1+l,c) fp16 + pool partials ----------------
__global__ void transpose_kernel(const float* __restrict__ x) {
    __shared__ float t[32][33];
    __shared__ float ps[8][32];
    int b  = blockIdx.z;
    int c0 = blockIdx.y * 32;
    int l0 = blockIdx.x * 32;
    int tx = threadIdx.x, ty = threadIdx.y;
    #pragma unroll
    for (int i = 0; i < 32; i += 8) {
        int c = c0 + ty + i, l = l0 + tx;
        t[ty + i][tx] = (l < LL) ? x[((size_t)b * Cc + c) * LL + l] : 0.f;
    }
    __syncthreads();
    #pragma unroll
    for (int i = 0; i < 32; i += 8) {
        int l = l0 + ty + i, c = c0 + tx;
        if (l < LL)
            d_X1h[((size_t)b * L1 + 1 + l) * Cc + c] = __float2half_rn(t[tx][ty + i]);
    }
    float p = t[tx][ty * 4] + t[tx][ty * 4 + 1] + t[tx][ty * 4 + 2] + t[tx][ty * 4 + 3];
    ps[ty][tx] = p;
    __syncthreads();
    if (ty == 0) {
        float s = 0.f;
        #pragma unroll
        for (int i = 0; i < 8; i++) s += ps[i][tx];
        d_poolp[((size_t)b * Cc + c0 + tx) * 7 + blockIdx.x] = s;
    }
}

// ---------------- pool finalize: X1 row 0 ----------------
__global__ void pool_final() {
    int idx = blockIdx.x * 256 + threadIdx.x;
    int b = idx >> 11, c = idx & (Cc - 1);
    float s = 0.f;
    #pragma unroll
    for (int j = 0; j < 7; j++) s += d_poolp[(size_t)idx * 7 + j];
    d_X1h[((size_t)b * L1) * Cc + c] = __float2half_rn(s * (1.f / (float)LL));
}

// ---------------- fused fp32 -> fp16 weight copies ----------------
#define WCP_N0  (HID * Cc / 4)
#define WCP_N1  (OUTC * HID / 4)
#define WCP_TOT (2 * WCP_N0 + 2 * WCP_N1)
__global__ void half_copy4(const float* __restrict__ s0, __half* __restrict__ d0,
                           const float* __restrict__ s1, __half* __restrict__ d1,
                           const float* __restrict__ s2, __half* __restrict__ d2,
                           const float* __restrict__ s3, __half* __restrict__ d3) {
    int i = blockIdx.x * 256 + threadIdx.x;
    const float* src; __half* dst; int off;
    if (i < WCP_N0)                       { src = s0; dst = d0; off = i; }
    else if (i < WCP_N0 + WCP_N1)         { src = s1; dst = d1; off = i - WCP_N0; }
    else if (i < 2 * WCP_N0 + WCP_N1)     { src = s2; dst = d2; off = i - WCP_N0 - WCP_N1; }
    else if (i < WCP_TOT)                 { src = s3; dst = d3; off = i - 2 * WCP_N0 - WCP_N1; }
    else return;
    float4 v = reinterpret_cast<const float4*>(src)[off];
    reinterpret_cast<__half2*>(dst)[off * 2    ] = __floats2half2_rn(v.x, v.y);
    reinterpret_cast<__half2*>(dst)[off * 2 + 1] = __floats2half2_rn(v.z, v.w);
}

// ---------------- BN finalize ----------------
__global__ void bn_final(const float* __restrict__ g, const float* __restrict__ bta,
                         float invN, int nch) {
    int i = blockIdx.x * 256 + threadIdx.x;
    int o0 = 2 * i, o1 = 2 * i + 1;
    float s0 = 0.f, q0 = 0.f, s1 = 0.f, q1 = 0.f;
    for (int ch = 0; ch < nch; ch++) {
        s0 += d_part_s[(size_t)ch * HID + o0]; q0 += d_part_q[(size_t)ch * HID + o0];
        s1 += d_part_s[(size_t)ch * HID + o1]; q1 += d_part_q[(size_t)ch * HID + o1];
    }
    float mu0 = s0 * invN, var0 = q0 * invN - mu0 * mu0;
    float mu1 = s1 * invN, var1 = q1 * invN - mu1 * mu1;
    float sc0 = g[o0] * rsqrtf(var0 + 1e-5f);
    float sc1 = g[o1] * rsqrtf(var1 + 1e-5f);
    d_hs[i] = __floats2half2_rn(sc0, sc1);
    d_hb[i] = __floats2half2_rn(bta[o0] - mu0 * sc0, bta[o1] - mu1 * sc1);
}

// ---------------- Z element (sum of split-K planes, fixed order) ----------------
__device__ __forceinline__ float zAt(size_t idx) {
    return d_ZP[idx] + d_ZP[ZPL + idx];
}

// ---------------- z_g extraction ----------------
__global__ void zg_kernel(float* __restrict__ out) {
    int idx = blockIdx.x * 256 + threadIdx.x;
    int b = idx >> 8, j = idx & 255;
    out[OFF_ZG + idx] = zAt(((size_t)b * L1) * OUTC + j);
}

// ---------------- feature L2 norm ----------------
__global__ void norm_kernel() {
    int bl = blockIdx.x;
    int b = bl / LL, l = bl % LL;
    float v = zAt(((size_t)b * L1 + 1 + l) * OUTC + threadIdx.x);
    float s = v * v;
    #pragma unroll
    for (int o = 16; o; o >>= 1) s += __shfl_down_sync(~0u, s, o);
    __shared__ float w[8];
    if ((threadIdx.x & 31) == 0) w[threadIdx.x >> 5] = s;
    __syncthreads();
    if (threadIdx.x == 0) {
        float t = 0.f;
        #pragma unroll
        for (int i = 0; i < 8; i++) t += w[i];
        d_nrm[bl] = sqrtf(t);
    }
}

// ---------------- softmax ----------------
__global__ void softmax_kernel(float* __restrict__ out) {
    int wg   = (blockIdx.x * blockDim.x + threadIdx.x) >> 5;
    int lane = threadIdx.x & 31;
    if (wg >= Bb * OUTC) return;
    int b = wg >> 8, j = wg & 255;
    float v[7];
    float mx = -INFINITY;
    #pragma unroll
    for (int i = 0; i < 7; i++) {
        int l = lane + i * 32;
        if (l < LL) {
            float n = d_nrm[b * LL + l];
            v[i] = zAt(((size_t)b * L1 + 1 + l) * OUTC + j) / fmaxf(n, 1e-12f);
            mx = fmaxf(mx, v[i]);
        } else v[i] = -INFINITY;
    }
    #pragma unroll
    for (int o = 16; o; o >>= 1) mx = fmaxf(mx, __shfl_xor_sync(~0u, mx, o));
    float s = 0.f;
    #pragma unroll
    for (int i = 0; i < 7; i++) { v[i] = expf(v[i] - mx); s += v[i]; }
    #pragma unroll
    for (int o = 16; o; o >>= 1) s += __shfl_xor_sync(~0u, s, o);
    float inv = 1.f / s;
    #pragma unroll
    for (int i = 0; i < 7; i++) {
        int l = lane + i * 32;
        if (l < LL) {
            float r = v[i] * inv;
            size_t idx = ((size_t)b * OUTC + j) * LL + l;
            out[OFF_ATTN + idx] = r;
            out[OFF_RAW  + idx] = r;
        }
    }
}

// ---------------- attention-value einsum (reads fp16 X1h) -> fp16 Vt ----------------
__global__ __launch_bounds__(256)
void attnval_kernel(const float* __restrict__ out) {
    const float* attn = out + OFF_ATTN;
    int h = blockIdx.x, b = blockIdx.y;
    __shared__ __half xs2[32][256];
    __shared__ float  as2[32][36];
    int tid = threadIdx.x;
    float acc[KH] = {};

    for (int l0 = 0; l0 < LL; l0 += 32) {
        int lmax = min(32, LL - l0);
        #pragma unroll
        for (int i = 0; i < 4; i++) {
            int task = tid + i * 256;
            int row = task >> 5, t = task & 31;
            if (l0 + row < LL) {
                const uint4* src = reinterpret_cast<const uint4*>(
                    d_X1h + ((size_t)b * L1 + 1 + l0 + row) * Cc + h * CH) + t;
                *(reinterpret_cast<uint4*>(&xs2[row][0]) + t) = *src;
            }
        }
        #pragma unroll
        for (int i = 0; i < 4; i++) {
            int k   = (tid >> 5) + i * 8;
            int col = tid & 31;
            float v = 0.f;
            if (l0 + col < LL)
                v = attn[(((size_t)b * NH + h) * KH + k) * LL + l0 + col];
            as2[col][k] = v;
        }
        __syncthreads();
        for (int l = 0; l < lmax; l++) {
            float xv = __half2float(xs2[l][tid]);
            #pragma unroll
            for (int k4 = 0; k4 < KH / 4; k4++) {
                float4 w = *reinterpret_cast<const float4*>(&as2[l][k4 * 4]);
                acc[k4 * 4 + 0] = fmaf(xv, w.x, acc[k4 * 4 + 0]);
                acc[k4 * 4 + 1] = fmaf(xv, w.y, acc[k4 * 4 + 1]);
                acc[k4 * 4 + 2] = fmaf(xv, w.z, acc[k4 * 4 + 2]);
                acc[k4 * 4 + 3] = fmaf(xv, w.w, acc[k4 * 4 + 3]);
            }
        }
        __syncthreads();
    }
    #pragma unroll
    for (int k = 0; k < KH; k++)
        d_Vth[((size_t)b * KH + k) * Cc + h * CH + tid] = __float2half_rn(acc[k]);
}

// ---------------- final permute + split-K reduce ----------------
__global__ void permute_kernel(float* __restrict__ out) {
    int idx = blockIdx.x * 256 + threadIdx.x;
    int b = idx >> 13;
    int rem = idx & 8191;
    int j = rem >> 5;
    int k = rem & 31;
    size_t src = ((size_t)b * KH + k) * OUTC + j;
    float s = 0.f;
    #pragma unroll
    for (int z = 0; z < 4; z++) s += d_P4[(size_t)z * N2 * OUTC + src];
    out[OFF_VAL + idx] = s;
}

// ---------------- launch ----------------
extern "C" void kernel_launch(void* const* d_in, const int* in_sizes, int n_in,
                              void* d_out, int out_size) {
    const float* x    = (const float*)d_in[0];
    const float* w1_p = (const float*)d_in[1];
    const float* g_p  = (const float*)d_in[2];
    const float* b_p  = (const float*)d_in[3];
    const float* w2_p = (const float*)d_in[4];
    const float* w1_o = (const float*)d_in[5];
    const float* g_o  = (const float*)d_in[6];
    const float* b_o  = (const float*)d_in[7];
    const float* w2_o = (const float*)d_in[8];
    float* out = (float*)d_out;

    float *pZP, *pP4, *pPs, *pPq;
    __half *pX1h, *pHh, *pVth, *pW1p, *pW2p, *pW1o, *pW2o;
    __half2 *pHs, *pHb;
    cudaGetSymbolAddress((void**)&pX1h, d_X1h);
    cudaGetSymbolAddress((void**)&pHh,  d_Hh);
    cudaGetSymbolAddress((void**)&pZP,  d_ZP);
    cudaGetSymbolAddress((void**)&pVth, d_Vth);
    cudaGetSymbolAddress((void**)&pP4,  d_P4);
    cudaGetSymbolAddress((void**)&pPs,  d_part_s);
    cudaGetSymbolAddress((void**)&pPq,  d_part_q);
    cudaGetSymbolAddress((void**)&pHs,  d_hs);
    cudaGetSymbolAddress((void**)&pHb,  d_hb);
    cudaGetSymbolAddress((void**)&pW1p, d_W1p);
    cudaGetSymbolAddress((void**)&pW2p, d_W2p);
    cudaGetSymbolAddress((void**)&pW1o, d_W1o);
    cudaGetSymbolAddress((void**)&pW2o, d_W2o);

    auto gemm1  = gemm_h<128, 128, true,  false, true,  1>;  // GEMM1/3: fp16 H + stats
    auto gemm2  = gemm_h<128, 128, false, true,  false, 2>;  // GEMM2: BN+ReLU, split-K2
    auto gemm4  = gemm_h<64,  128, false, true,  false, 4>;  // GEMM4: BN+ReLU, split-K4
    constexpr int SM_128 = 4 * (128 * 80 + 128 * 80);   // 81920
    constexpr int SM_64  = 4 * (64  * 80 + 128 * 80);   // 61440
    cudaFuncSetAttribute(gemm1, cudaFuncAttributeMaxDynamicSharedMemorySize, SM_128);
    cudaFuncSetAttribute(gemm2, cudaFuncAttributeMaxDynamicSharedMemorySize, SM_128);
    cudaFuncSetAttribute(gemm4, cudaFuncAttributeMaxDynamicSharedMemorySize, SM_64);

    // weights -> fp16 (single fused launch)
    half_copy4<<<(WCP_TOT + 255) / 256, 256>>>(w1_p, pW1p, w2_p, pW2p,
                                               w1_o, pW1o, w2_o, pW2o);

    // 0) transpose + pool partials, then pool finalize (X1 row 0)
    transpose_kernel<<<dim3(7, Cc / 32, Bb), dim3(32, 8)>>>(x);
    pool_final<<<(Bb * Cc) / 256, 256>>>();

    // 1) H = X1 @ w1_p^T (12608 x 2048 x 2048), fp16 out + fused BN stats
    gemm1<<<dim3(HID / 128, (N1 + 127) / 128), 256, SM_128>>>(
        pX1h, pW1p, pHh, N1, HID, nullptr, nullptr, pPs, pPq);

    // 2) BN finalize (packed half2 scale/shift)
    bn_final<<<HID / 512, 256>>>(g_p, b_p, 1.f / (float)N1, (N1 + 127) / 128);

    // 3) Z partials = relu(bn(H)) @ w2_p^T, split-K x2 -> 396 CTAs
    gemm2<<<dim3(OUTC / 128, (N1 + 127) / 128, 2), 256, SM_128>>>(
        pHh, pW2p, pZP, N1, OUTC, pHs, pHb, nullptr, nullptr);

    // 4) z_g; norms; softmax (consumers sum the two Z planes)
    zg_kernel<<<(Bb * OUTC) / 256, 256>>>(out);
    norm_kernel<<<Bb * LL, 256>>>();
    softmax_kernel<<<(Bb * OUTC) / 8, 256>>>(out);

    // 5) attention value (fp16 X1h input) -> fp16 Vt
    attnval_kernel<<<dim3(NH, Bb), 256>>>(out);

    // 6) H = Vt @ w1_o^T (2048 x 2048 x 2048), fp16 out + fused BN stats
    gemm1<<<dim3(HID / 128, N2 / 128), 256, SM_128>>>(
        pVth, pW1o, pHh, N2, HID, nullptr, nullptr, pPs, pPq);

    // 7) BN finalize 2
    bn_final<<<HID / 512, 256>>>(g_o, b_o, 1.f / (float)N2, N2 / 128);

    // 8) C4 partials = relu(bn(H)) @ w2_o^T, split-K x4 -> 256 CTAs
    gemm4<<<dim3(OUTC / 128, N2 / 64, 4), 256, SM_64>>>(
        pHh, pW2o, pP4, N2, OUTC, pHs, pHb, nullptr, nullptr);

    // 9) permute + split-K reduce to obj_val layout
    permute_kernel<<<(Bb * OUTC * KH) / 256, 256>>>(out);
}

// round 16
// speedup vs baseline: 1.0893x; 1.0307x over previous
#include <cuda_runtime.h>
#include <cuda_fp16.h>
#include <math.h>
#include <stdint.h>

// ---------------- problem constants ----------------
#define Bb    64
#define Cc    2048
#define LL    196
#define L1    197
#define HID   2048
#define OUTC  256
#define NH    8
#define CH    (Cc / NH)
#define KH    (OUTC / NH)
#define N1    (Bb * L1)     // 12608
#define N2    (Bb * KH)     // 2048
#define KDIM  2048

#define OFF_ZG    0
#define OFF_VAL   (Bb * OUTC)
#define OFF_ATTN  (OFF_VAL + Bb * OUTC * KH)
#define OFF_RAW   (OFF_ATTN + Bb * NH * KH * LL)

// ---------------- device scratch ----------------
__device__ __half  d_X1h[(size_t)N1 * Cc];    // (b, l, c) fp16
__device__ __half  d_Hh[(size_t)N1 * HID];    // H pre-BN fp16
__device__ float   d_Z [(size_t)N1 * OUTC];
__device__ __half  d_Vth[(size_t)N2 * Cc];
__device__ float   d_P4[(size_t)4 * N2 * OUTC];   // GEMM4 split-K partials
__device__ float   d_nrm[Bb * LL];
__device__ float   d_part_s[128 * HID];
__device__ float   d_part_q[128 * HID];
__device__ __half2 d_hs[HID / 2];             // BN scale, packed pairs
__device__ __half2 d_hb[HID / 2];             // BN shift, packed pairs
__device__ float   d_poolp[Bb * Cc * 7];      // pool partials per l-block
__device__ __half  d_W1p[(size_t)HID * Cc];
__device__ __half  d_W2p[(size_t)OUTC * HID];
__device__ __half  d_W1o[(size_t)HID * Cc];
__device__ __half  d_W2o[(size_t)OUTC * HID];

// ---------------- helpers ----------------
__device__ __forceinline__ uint32_t smem_u32(const void* p) {
    return (uint32_t)__cvta_generic_to_shared(p);
}

__device__ __forceinline__ void cpasync16_s(uint32_t saddr, const void* g, bool pred) {
    int sz = pred ? 16 : 0;
    asm volatile("cp.async.cg.shared.global [%0], [%1], 16, %2;"
                 :: "r"(saddr), "l"(g), "r"(sz));
}

__device__ __forceinline__ void ldsm4(uint32_t* r, uint32_t addr) {
    asm volatile("ldmatrix.sync.aligned.m8n8.x4.shared.b16 {%0,%1,%2,%3}, [%4];"
                 : "=r"(r[0]), "=r"(r[1]), "=r"(r[2]), "=r"(r[3]) : "r"(addr));
}

__device__ __forceinline__ void mma16816(float* d, const uint32_t* a,
                                         uint32_t b0, uint32_t b1) {
    asm volatile(
        "mma.sync.aligned.m16n8k16.row.col.f32.f16.f16.f32 "
        "{%0,%1,%2,%3}, {%4,%5,%6,%7}, {%8,%9}, {%0,%1,%2,%3};"
        : "+f"(d[0]), "+f"(d[1]), "+f"(d[2]), "+f"(d[3])
        : "r"(a[0]), "r"(a[1]), "r"(a[2]), "r"(a[3]), "r"(b0), "r"(b1));
}

__device__ __forceinline__ uint32_t bnrelu2(uint32_t h, __half2 s, __half2 o) {
    __half2 v = *reinterpret_cast<__half2*>(&h);
    v = __hmax2(__hfma2(v, s, o), __half2half2(__ushort_as_half(0)));
    return *reinterpret_cast<uint32_t*>(&v);
}

// ================= fp16 mma.sync GEMM (R12-proven: BK=32, 4-slot, 2-ahead) ====
template <int ROWS, int COLS, bool HOUT, bool BNRELU, bool STATS, int SPLIT>
__global__ __launch_bounds__(256, 2)
void gemm_h(const __half* __restrict__ A, const __half* __restrict__ W,
            void* __restrict__ Cout, int R, int Cols,
            const __half2* __restrict__ hs, const __half2* __restrict__ hb,
            float* __restrict__ part_s, float* __restrict__ part_q)
{
    constexpr int WN  = COLS / 64;
    constexpr int WM  = 8 / WN;
    constexpr int MI  = ROWS / (16 * WM);
    constexpr int A_STG = ROWS * 80;
    constexpr int B_STG = COLS * 80;
    constexpr int B_OFF = 4 * A_STG;
    constexpr int NIT = KDIM / (32 * SPLIT);

    extern __shared__ char sm[];
    const uint32_t sbase = smem_u32(sm);
    const int tid  = threadIdx.x;
    const int warp = tid >> 5, lane = tid & 31;
    const int tg = lane & 3;
    const int wm = warp / WN, wn = warp % WN;
    const int row0 = blockIdx.y * ROWS;
    const int col0 = blockIdx.x * COLS;
    const int kOff = (SPLIT > 1) ? (int)blockIdx.z * (KDIM / SPLIT) : 0;

    float acc[MI][8][4] = {};

    auto loadStage = [&](int j) {
        const int st = j & 3;
        const uint32_t aB = sbase + st * A_STG;
        const uint32_t bB = sbase + B_OFF + st * B_STG;
        const __half* Aj = A + (size_t)row0 * KDIM + kOff + j * 32;
        const __half* Wj = W + (size_t)col0 * KDIM + kOff + j * 32;
        #pragma unroll
        for (int i = 0; i < ROWS / 64; i++) {
            int task = tid + i * 256;
            int r = task >> 2, ch = task & 3;
            bool p = (row0 + r) < R;
            cpasync16_s(aB + r * 80 + ch * 16,
                        Aj + (size_t)(p ? r : 0) * KDIM + ch * 8, p);
        }
        #pragma unroll
        for (int i = 0; i < COLS / 64; i++) {
            int task = tid + i * 256;
            int r = task >> 2, ch = task & 3;
            cpasync16_s(bB + r * 80 + ch * 16,
                        Wj + (size_t)r * KDIM + ch * 8, true);
        }
        asm volatile("cp.async.commit_group;");
    };

    loadStage(0);
    loadStage(1);

    for (int it = 0; it < NIT; it++) {
        int j = it + 2;
        if (j < NIT) {
            loadStage(j);                              // issue loads FIRST
            asm volatile("cp.async.wait_group 2;");    // then block on stage `it`
        } else {
            asm volatile("cp.async.wait_group 0;");
        }
        __syncthreads();

        const int st = it & 3;
        const uint32_t aB = sbase + st * A_STG;
        const uint32_t bB = sbase + B_OFF + st * B_STG;

        #pragma unroll
        for (int kt = 0; kt < 2; kt++) {
            uint32_t af[MI][4], bf[4][4];
            #pragma unroll
            for (int mi = 0; mi < MI; mi++) {
                int rowb = wm * (MI * 16) + mi * 16 + (lane & 15);
                uint32_t addr = aB + rowb * 80 + kt * 32 + ((lane >> 4) << 4);
                ldsm4(af[mi], addr);
            }
            if (BNRELU) {
                const int pidx = kOff / 2 + it * 16 + kt * 8 + tg;
                __half2 s0 = hs[pidx],     o0 = hb[pidx];
                __half2 s1 = hs[pidx + 4], o1 = hb[pidx + 4];
                #pragma unroll
                for (int mi = 0; mi < MI; mi++) {
                    af[mi][0] = bnrelu2(af[mi][0], s0, o0);
                    af[mi][1] = bnrelu2(af[mi][1], s0, o0);
                    af[mi][2] = bnrelu2(af[mi][2], s1, o1);
                    af[mi][3] = bnrelu2(af[mi][3], s1, o1);
                }
            }
            #pragma unroll
            for (int jp = 0; jp < 4; jp++) {
                int rown = wn * 64 + jp * 16 + (lane & 7) + ((lane >> 4) << 3);
                uint32_t addr = bB + rown * 80 + kt * 32 + (((lane >> 3) & 1) << 4);
                ldsm4(bf[jp], addr);
            }
            #pragma unroll
            for (int mi = 0; mi < MI; mi++)
                #pragma unroll
                for (int jp = 0; jp < 4; jp++) {
                    mma16816(acc[mi][jp * 2],     af[mi], bf[jp][0], bf[jp][1]);
                    mma16816(acc[mi][jp * 2 + 1], af[mi], bf[jp][2], bf[jp][3]);
                }
        }
    }

    if (STATS) {
        float sl[8][2] = {}, ql[8][2] = {};
        #pragma unroll
        for (int nj = 0; nj < 8; nj++)
            #pragma unroll
            for (int mi = 0; mi < MI; mi++) {
                float v0 = acc[mi][nj][0], v1 = acc[mi][nj][1];
                float v2 = acc[mi][nj][2], v3 = acc[mi][nj][3];
                sl[nj][0] += v0 + v2;  ql[nj][0] += v0 * v0 + v2 * v2;
                sl[nj][1] += v1 + v3;  ql[nj][1] += v1 * v1 + v3 * v3;
            }
        #pragma unroll
        for (int off = 4; off < 32; off <<= 1)
            #pragma unroll
            for (int nj = 0; nj < 8; nj++) {
                sl[nj][0] += __shfl_xor_sync(~0u, sl[nj][0], off);
                sl[nj][1] += __shfl_xor_sync(~0u, sl[nj][1], off);
                ql[nj][0] += __shfl_xor_sync(~0u, ql[nj][0], off);
                ql[nj][1] += __shfl_xor_sync(~0u, ql[nj][1], off);
            }
        __syncthreads();
        float* sred = reinterpret_cast<float*>(sm);
        if (lane < 4) {
            #pragma unroll
            for (int nj = 0; nj < 8; nj++) {
                int col = wn * 64 + nj * 8 + lane * 2;
                sred[wm * COLS + col]     = sl[nj][0];
                sred[wm * COLS + col + 1] = sl[nj][1];
                sred[WM * COLS + wm * COLS + col]     = ql[nj][0];
                sred[WM * COLS + wm * COLS + col + 1] = ql[nj][1];
            }
        }
        __syncthreads();
        if (tid < COLS) {
            float s = 0.f, q = 0.f;
            #pragma unroll
            for (int w = 0; w < WM; w++) {
                s += sred[w * COLS + tid];
                q += sred[WM * COLS + w * COLS + tid];
            }
            part_s[(size_t)blockIdx.y * Cols + col0 + tid] = s;
            part_q[(size_t)blockIdx.y * Cols + col0 + tid] = q;
        }
    }

    const size_t splitOff = (SPLIT > 1) ? (size_t)blockIdx.z * R * Cols : 0;
    #pragma unroll
    for (int mi = 0; mi < MI; mi++) {
        int rbase = row0 + wm * (MI * 16) + mi * 16 + (lane >> 2);
        #pragma unroll
        for (int nj = 0; nj < 8; nj++) {
            int c = col0 + wn * 64 + nj * 8 + (lane & 3) * 2;
            if (HOUT) {
                __half* Ch = (__half*)Cout;
                if (rbase < R)
                    *reinterpret_cast<__half2*>(&Ch[(size_t)rbase * Cols + c]) =
                        __floats2half2_rn(acc[mi][nj][0], acc[mi][nj][1]);
                if (rbase + 8 < R)
                    *reinterpret_cast<__half2*>(&Ch[(size_t)(rbase + 8) * Cols + c]) =
                        __floats2half2_rn(acc[mi][nj][2], acc[mi][nj][3]);
            } else {
                float* Cf = (float*)Cout + splitOff;
                if (rbase < R)
                    *reinterpret_cast<float2*>(&Cf[(size_t)rbase * Cols + c]) =
                        make_float2(acc[mi][nj][0], acc[mi][nj][1]);
                if (rbase + 8 < R)
                    *reinterpret_cast<float2*>(&Cf[(size_t)(rbase + 8) * Cols + c]) =
                        make_float2(acc[mi][nj][2], acc[mi][nj][3]);
            }
        }
    }
}

// ---------------- transpose (b,c,l)->(b,1+l,c) fp16 + pool partials ----------------
__global__ void transpose_kernel(const float* __restrict__ x) {
    __shared__ float t[32][33];
    __shared__ float ps[8][32];
    int b  = blockIdx.z;
    int c0 = blockIdx.y * 32;
    int l0 = blockIdx.x * 32;
    int tx = threadIdx.x, ty = threadIdx.y;
    #pragma unroll
    for (int i = 0; i < 32; i += 8) {
        int c = c0 + ty + i, l = l0 + tx;
        t[ty + i][tx] = (l < LL) ? x[((size_t)b * Cc + c) * LL + l] : 0.f;
    }
    __syncthreads();
    #pragma unroll
    for (int i = 0; i < 32; i += 8) {
        int l = l0 + ty + i, c = c0 + tx;
        if (l < LL)
            d_X1h[((size_t)b * L1 + 1 + l) * Cc + c] = __float2half_rn(t[tx][ty + i]);
    }
    float p = t[tx][ty * 4] + t[tx][ty * 4 + 1] + t[tx][ty * 4 + 2] + t[tx][ty * 4 + 3];
    ps[ty][tx] = p;
    __syncthreads();
    if (ty == 0) {
        float s = 0.f;
        #pragma unroll
        for (int i = 0; i < 8; i++) s += ps[i][tx];
        d_poolp[((size_t)b * Cc + c0 + tx) * 7 + blockIdx.x] = s;
    }
}

// ---------------- pool finalize: X1 row 0 ----------------
__global__ void pool_final() {
    int idx = blockIdx.x * 256 + threadIdx.x;
    int b = idx >> 11, c = idx & (Cc - 1);
    float s = 0.f;
    #pragma unroll
    for (int j = 0; j < 7; j++) s += d_poolp[(size_t)idx * 7 + j];
    d_X1h[((size_t)b * L1) * Cc + c] = __float2half_rn(s * (1.f / (float)LL));
}

// ---------------- fused fp32 -> fp16 weight copies ----------------
#define WCP_N0  (HID * Cc / 4)
#define WCP_N1  (OUTC * HID / 4)
#define WCP_TOT (2 * WCP_N0 + 2 * WCP_N1)
__global__ void half_copy4(const float* __restrict__ s0, __half* __restrict__ d0,
                           const float* __restrict__ s1, __half* __restrict__ d1,
                           const float* __restrict__ s2, __half* __restrict__ d2,
                           const float* __restrict__ s3, __half* __restrict__ d3) {
    int i = blockIdx.x * 256 + threadIdx.x;
    const float* src; __half* dst; int off;
    if (i < WCP_N0)                       { src = s0; dst = d0; off = i; }
    else if (i < WCP_N0 + WCP_N1)         { src = s1; dst = d1; off = i - WCP_N0; }
    else if (i < 2 * WCP_N0 + WCP_N1)     { src = s2; dst = d2; off = i - WCP_N0 - WCP_N1; }
    else if (i < WCP_TOT)                 { src = s3; dst = d3; off = i - 2 * WCP_N0 - WCP_N1; }
    else return;
    float4 v = reinterpret_cast<const float4*>(src)[off];
    reinterpret_cast<__half2*>(dst)[off * 2    ] = __floats2half2_rn(v.x, v.y);
    reinterpret_cast<__half2*>(dst)[off * 2 + 1] = __floats2half2_rn(v.z, v.w);
}

// ---------------- BN finalize (4 workers per channel, fixed-order combine) ----
__global__ void bn_final(const float* __restrict__ g, const float* __restrict__ bta,
                         float invN, int nch) {
    // block: 256 threads = 64 channels x 4 workers; grid HID/64 = 32 blocks
    int tid = threadIdx.x;
    int cl = tid >> 2, w = tid & 3;
    int o = blockIdx.x * 64 + cl;
    float s = 0.f, q = 0.f;
    for (int ch = w; ch < nch; ch += 4) {
        s += d_part_s[(size_t)ch * HID + o];
        q += d_part_q[(size_t)ch * HID + o];
    }
    // combine workers (lanes cl*4 + w within the warp): (s0+s2)+(s1+s3)
    s += __shfl_down_sync(~0u, s, 2);
    q += __shfl_down_sync(~0u, q, 2);
    s += __shfl_down_sync(~0u, s, 1);
    q += __shfl_down_sync(~0u, q, 1);
    if (w == 0) {
        float mu  = s * invN;
        float var = q * invN - mu * mu;
        float sc  = g[o] * rsqrtf(var + 1e-5f);
        reinterpret_cast<__half*>(d_hs)[o] = __float2half_rn(sc);
        reinterpret_cast<__half*>(d_hb)[o] = __float2half_rn(bta[o] - mu * sc);
    }
}

// ---------------- feature L2 norm ----------------
__global__ void norm_kernel() {
    int bl = blockIdx.x;
    int b = bl / LL, l = bl % LL;
    float v = d_Z[((size_t)b * L1 + 1 + l) * OUTC + threadIdx.x];
    float s = v * v;
    #pragma unroll
    for (int o = 16; o; o >>= 1) s += __shfl_down_sync(~0u, s, o);
    __shared__ float w[8];
    if ((threadIdx.x & 31) == 0) w[threadIdx.x >> 5] = s;
    __syncthreads();
    if (threadIdx.x == 0) {
        float t = 0.f;
        #pragma unroll
        for (int i = 0; i < 8; i++) t += w[i];
        d_nrm[bl] = sqrtf(t);
    }
}

// ---------------- softmax (+ fused z_g write, one warp per (b,j)) ----------------
__global__ void softmax_kernel(float* __restrict__ out) {
    int wg   = (blockIdx.x * blockDim.x + threadIdx.x) >> 5;
    int lane = threadIdx.x & 31;
    if (wg >= Bb * OUTC) return;
    int b = wg >> 8, j = wg & 255;
    if (lane == 0)
        out[OFF_ZG + b * OUTC + j] = d_Z[((size_t)b * L1) * OUTC + j];
    float v[7];
    float mx = -INFINITY;
    #pragma unroll
    for (int i = 0; i < 7; i++) {
        int l = lane + i * 32;
        if (l < LL) {
            float n = d_nrm[b * LL + l];
            v[i] = d_Z[((size_t)b * L1 + 1 + l) * OUTC + j] / fmaxf(n, 1e-12f);
            mx = fmaxf(mx, v[i]);
        } else v[i] = -INFINITY;
    }
    #pragma unroll
    for (int o = 16; o; o >>= 1) mx = fmaxf(mx, __shfl_xor_sync(~0u, mx, o));
    float s = 0.f;
    #pragma unroll
    for (int i = 0; i < 7; i++) { v[i] = expf(v[i] - mx); s += v[i]; }
    #pragma unroll
    for (int o = 16; o; o >>= 1) s += __shfl_xor_sync(~0u, s, o);
    float inv = 1.f / s;
    #pragma unroll
    for (int i = 0; i < 7; i++) {
        int l = lane + i * 32;
        if (l < LL) {
            float r = v[i] * inv;
            size_t idx = ((size_t)b * OUTC + j) * LL + l;
            out[OFF_ATTN + idx] = r;
            out[OFF_RAW  + idx] = r;
        }
    }
}

// ---------------- attention-value einsum (reads fp16 X1h) -> fp16 Vt ----------------
__global__ __launch_bounds__(256)
void attnval_kernel(const float* __restrict__ out) {
    const float* attn = out + OFF_ATTN;
    int h = blockIdx.x, b = blockIdx.y;
    __shared__ __half xs2[32][256];
    __shared__ float  as2[32][36];
    int tid = threadIdx.x;
    float acc[KH] = {};

    for (int l0 = 0; l0 < LL; l0 += 32) {
        int lmax = min(32, LL - l0);
        #pragma unroll
        for (int i = 0; i < 4; i++) {
            int task = tid + i * 256;
            int row = task >> 5, t = task & 31;
            if (l0 + row < LL) {
                const uint4* src = reinterpret_cast<const uint4*>(
                    d_X1h + ((size_t)b * L1 + 1 + l0 + row) * Cc + h * CH) + t;
                *(reinterpret_cast<uint4*>(&xs2[row][0]) + t) = *src;
            }
        }
        #pragma unroll
        for (int i = 0; i < 4; i++) {
            int k   = (tid >> 5) + i * 8;
            int col = tid & 31;
            float v = 0.f;
            if (l0 + col < LL)
                v = attn[(((size_t)b * NH + h) * KH + k) * LL + l0 + col];
            as2[col][k] = v;
        }
        __syncthreads();
        for (int l = 0; l < lmax; l++) {
            float xv = __half2float(xs2[l][tid]);
            #pragma unroll
            for (int k4 = 0; k4 < KH / 4; k4++) {
                float4 w = *reinterpret_cast<const float4*>(&as2[l][k4 * 4]);
                acc[k4 * 4 + 0] = fmaf(xv, w.x, acc[k4 * 4 + 0]);
                acc[k4 * 4 + 1] = fmaf(xv, w.y, acc[k4 * 4 + 1]);
                acc[k4 * 4 + 2] = fmaf(xv, w.z, acc[k4 * 4 + 2]);
                acc[k4 * 4 + 3] = fmaf(xv, w.w, acc[k4 * 4 + 3]);
            }
        }
        __syncthreads();
    }
    #pragma unroll
    for (int k = 0; k < KH; k++)
        d_Vth[((size_t)b * KH + k) * Cc + h * CH + tid] = __float2half_rn(acc[k]);
}

// ---------------- final permute + split-K reduce ----------------
__global__ void permute_kernel(float* __restrict__ out) {
    int idx = blockIdx.x * 256 + threadIdx.x;
    int b = idx >> 13;
    int rem = idx & 8191;
    int j = rem >> 5;
    int k = rem & 31;
    size_t src = ((size_t)b * KH + k) * OUTC + j;
    float s = 0.f;
    #pragma unroll
    for (int z = 0; z < 4; z++) s += d_P4[(size_t)z * N2 * OUTC + src];
    out[OFF_VAL + idx] = s;
}

// ---------------- launch ----------------
extern "C" void kernel_launch(void* const* d_in, const int* in_sizes, int n_in,
                              void* d_out, int out_size) {
    const float* x    = (const float*)d_in[0];
    const float* w1_p = (const float*)d_in[1];
    const float* g_p  = (const float*)d_in[2];
    const float* b_p  = (const float*)d_in[3];
    const float* w2_p = (const float*)d_in[4];
    const float* w1_o = (const float*)d_in[5];
    const float* g_o  = (const float*)d_in[6];
    const float* b_o  = (const float*)d_in[7];
    const float* w2_o = (const float*)d_in[8];
    float* out = (float*)d_out;

    float *pZ, *pP4, *pPs, *pPq;
    __half *pX1h, *pHh, *pVth, *pW1p, *pW2p, *pW1o, *pW2o;
    __half2 *pHs, *pHb;
    cudaGetSymbolAddress((void**)&pX1h, d_X1h);
    cudaGetSymbolAddress((void**)&pHh,  d_Hh);
    cudaGetSymbolAddress((void**)&pZ,   d_Z);
    cudaGetSymbolAddress((void**)&pVth, d_Vth);
    cudaGetSymbolAddress((void**)&pP4,  d_P4);
    cudaGetSymbolAddress((void**)&pPs,  d_part_s);
    cudaGetSymbolAddress((void**)&pPq,  d_part_q);
    cudaGetSymbolAddress((void**)&pHs,  d_hs);
    cudaGetSymbolAddress((void**)&pHb,  d_hb);
    cudaGetSymbolAddress((void**)&pW1p, d_W1p);
    cudaGetSymbolAddress((void**)&pW2p, d_W2p);
    cudaGetSymbolAddress((void**)&pW1o, d_W1o);
    cudaGetSymbolAddress((void**)&pW2o, d_W2o);

    auto gemm1  = gemm_h<128, 128, true,  false, true,  1>;  // GEMM1/3: fp16 H + stats
    auto gemm2  = gemm_h<128, 128, false, true,  false, 1>;  // GEMM2: BN+ReLU fused A
    auto gemm4  = gemm_h<64,  128, false, true,  false, 4>;  // GEMM4: BN+ReLU, split-K4
    constexpr int SM_128 = 4 * (128 * 80 + 128 * 80);   // 81920
    constexpr int SM_64  = 4 * (64  * 80 + 128 * 80);   // 61440
    cudaFuncSetAttribute(gemm1, cudaFuncAttributeMaxDynamicSharedMemorySize, SM_128);
    cudaFuncSetAttribute(gemm2, cudaFuncAttributeMaxDynamicSharedMemorySize, SM_128);
    cudaFuncSetAttribute(gemm4, cudaFuncAttributeMaxDynamicSharedMemorySize, SM_64);

    // weights -> fp16 (single fused launch)
    half_copy4<<<(WCP_TOT + 255) / 256, 256>>>(w1_p, pW1p, w2_p, pW2p,
                                               w1_o, pW1o, w2_o, pW2o);

    // 0) transpose + pool partials, then pool finalize (X1 row 0)
    transpose_kernel<<<dim3(7, Cc / 32, Bb), dim3(32, 8)>>>(x);
    pool_final<<<(Bb * Cc) / 256, 256>>>();

    // 1) H = X1 @ w1_p^T (12608 x 2048 x 2048), fp16 out + fused BN stats
    gemm1<<<dim3(HID / 128, (N1 + 127) / 128), 256, SM_128>>>(
        pX1h, pW1p, pHh, N1, HID, nullptr, nullptr, pPs, pPq);

    // 2) BN finalize (4 workers/channel)
    bn_final<<<HID / 64, 256>>>(g_p, b_p, 1.f / (float)N1, (N1 + 127) / 128);

    // 3) Z = relu(bn(H)) @ w2_p^T, BN+ReLU fused into A fragments
    gemm2<<<dim3(OUTC / 128, (N1 + 127) / 128), 256, SM_128>>>(
        pHh, pW2p, pZ, N1, OUTC, pHs, pHb, nullptr, nullptr);

    // 4) norms; softmax (+ fused z_g)
    norm_kernel<<<Bb * LL, 256>>>();
    softmax_kernel<<<(Bb * OUTC) / 8, 256>>>(out);

    // 5) attention value (fp16 X1h input) -> fp16 Vt
    attnval_kernel<<<dim3(NH, Bb), 256>>>(out);

    // 6) H = Vt @ w1_o^T (2048 x 2048 x 2048), fp16 out + fused BN stats
    gemm1<<<dim3(HID / 128, N2 / 128), 256, SM_128>>>(
        pVth, pW1o, pHh, N2, HID, nullptr, nullptr, pPs, pPq);

    // 7) BN finalize 2
    bn_final<<<HID / 64, 256>>>(g_o, b_o, 1.f / (float)N2, N2 / 128);

    // 8) C4 partials = relu(bn(H)) @ w2_o^T, split-K x4 -> 256 CTAs
    gemm4<<<dim3(OUTC / 128, N2 / 64, 4), 256, SM_64>>>(
        pHh, pW2o, pP4, N2, OUTC, pHs, pHb, nullptr, nullptr);

    // 9) permute + split-K reduce to obj_val layout
    permute_kernel<<<(Bb * OUTC * KH) / 256, 256>>>(out);
}

// round 17
// speedup vs baseline: 1.1177x; 1.0261x over previous
#include <cuda_runtime.h>
#include <cuda_fp16.h>
#include <math.h>
#include <stdint.h>

// ---------------- problem constants ----------------
#define Bb    64
#define Cc    2048
#define LL    196
#define L1    197
#define HID   2048
#define OUTC  256
#define NH    8
#define CH    (Cc / NH)
#define KH    (OUTC / NH)
#define N1    (Bb * L1)     // 12608
#define N2    (Bb * KH)     // 2048
#define KDIM  2048

#define OFF_ZG    0
#define OFF_VAL   (Bb * OUTC)
#define OFF_ATTN  (OFF_VAL + Bb * OUTC * KH)
#define OFF_RAW   (OFF_ATTN + Bb * NH * KH * LL)

// ---------------- device scratch ----------------
__device__ __half  d_X1h[(size_t)N1 * Cc];    // (b, l, c) fp16
__device__ __half  d_Hh[(size_t)N1 * HID];    // H pre-BN fp16
__device__ float   d_Z [(size_t)N1 * OUTC];
__device__ __half  d_Vth[(size_t)N2 * Cc];
__device__ float   d_P4[(size_t)4 * N2 * OUTC];   // GEMM4 split-K partials
__device__ float   d_nrm[Bb * LL];
__device__ float   d_part_s[128 * HID];
__device__ float   d_part_q[128 * HID];
__device__ __half2 d_hs[HID / 2];             // BN scale, packed pairs
__device__ __half2 d_hb[HID / 2];             // BN shift, packed pairs
__device__ float   d_poolp[Bb * Cc * 7];      // pool partials per l-block
__device__ __half  d_W1p[(size_t)HID * Cc];
__device__ __half  d_W2p[(size_t)OUTC * HID];
__device__ __half  d_W1o[(size_t)HID * Cc];
__device__ __half  d_W2o[(size_t)OUTC * HID];

// ---------------- helpers ----------------
__device__ __forceinline__ uint32_t smem_u32(const void* p) {
    return (uint32_t)__cvta_generic_to_shared(p);
}

__device__ __forceinline__ void cpasync16_s(uint32_t saddr, const void* g, bool pred) {
    int sz = pred ? 16 : 0;
    asm volatile("cp.async.cg.shared.global [%0], [%1], 16, %2;"
                 :: "r"(saddr), "l"(g), "r"(sz));
}

__device__ __forceinline__ void ldsm4(uint32_t* r, uint32_t addr) {
    asm volatile("ldmatrix.sync.aligned.m8n8.x4.shared.b16 {%0,%1,%2,%3}, [%4];"
                 : "=r"(r[0]), "=r"(r[1]), "=r"(r[2]), "=r"(r[3]) : "r"(addr));
}

__device__ __forceinline__ void mma16816(float* d, const uint32_t* a,
                                         uint32_t b0, uint32_t b1) {
    asm volatile(
        "mma.sync.aligned.m16n8k16.row.col.f32.f16.f16.f32 "
        "{%0,%1,%2,%3}, {%4,%5,%6,%7}, {%8,%9}, {%0,%1,%2,%3};"
        : "+f"(d[0]), "+f"(d[1]), "+f"(d[2]), "+f"(d[3])
        : "r"(a[0]), "r"(a[1]), "r"(a[2]), "r"(a[3]), "r"(b0), "r"(b1));
}

__device__ __forceinline__ uint32_t bnrelu2(uint32_t h, __half2 s, __half2 o) {
    __half2 v = *reinterpret_cast<__half2*>(&h);
    v = __hmax2(__hfma2(v, s, o), __half2half2(__ushort_as_half(0)));
    return *reinterpret_cast<uint32_t*>(&v);
}

// ================= fp16 mma.sync GEMM (R12-proven: BK=32, 4-slot, 2-ahead) ====
template <int ROWS, int COLS, bool HOUT, bool BNRELU, bool STATS, int SPLIT>
__global__ __launch_bounds__(256, 2)
void gemm_h(const __half* __restrict__ A, const __half* __restrict__ W,
            void* __restrict__ Cout, int R, int Cols,
            const __half2* __restrict__ hs, const __half2* __restrict__ hb,
            float* __restrict__ part_s, float* __restrict__ part_q)
{
    constexpr int WN  = COLS / 64;
    constexpr int WM  = 8 / WN;
    constexpr int MI  = ROWS / (16 * WM);
    constexpr int A_STG = ROWS * 80;
    constexpr int B_STG = COLS * 80;
    constexpr int B_OFF = 4 * A_STG;
    constexpr int NIT = KDIM / (32 * SPLIT);

    extern __shared__ char sm[];
    const uint32_t sbase = smem_u32(sm);
    const int tid  = threadIdx.x;
    const int warp = tid >> 5, lane = tid & 31;
    const int tg = lane & 3;
    const int wm = warp / WN, wn = warp % WN;
    const int row0 = blockIdx.y * ROWS;
    const int col0 = blockIdx.x * COLS;
    const int kOff = (SPLIT > 1) ? (int)blockIdx.z * (KDIM / SPLIT) : 0;

    float acc[MI][8][4] = {};

    auto loadStage = [&](int j) {
        const int st = j & 3;
        const uint32_t aB = sbase + st * A_STG;
        const uint32_t bB = sbase + B_OFF + st * B_STG;
        const __half* Aj = A + (size_t)row0 * KDIM + kOff + j * 32;
        const __half* Wj = W + (size_t)col0 * KDIM + kOff + j * 32;
        #pragma unroll
        for (int i = 0; i < ROWS / 64; i++) {
            int task = tid + i * 256;
            int r = task >> 2, ch = task & 3;
            bool p = (row0 + r) < R;
            cpasync16_s(aB + r * 80 + ch * 16,
                        Aj + (size_t)(p ? r : 0) * KDIM + ch * 8, p);
        }
        #pragma unroll
        for (int i = 0; i < COLS / 64; i++) {
            int task = tid + i * 256;
            int r = task >> 2, ch = task & 3;
            cpasync16_s(bB + r * 80 + ch * 16,
                        Wj + (size_t)r * KDIM + ch * 8, true);
        }
        asm volatile("cp.async.commit_group;");
    };

    loadStage(0);
    loadStage(1);

    for (int it = 0; it < NIT; it++) {
        int j = it + 2;
        if (j < NIT) {
            loadStage(j);                              // issue loads FIRST
            asm volatile("cp.async.wait_group 2;");    // then block on stage `it`
        } else {
            asm volatile("cp.async.wait_group 0;");
        }
        __syncthreads();

        const int st = it & 3;
        const uint32_t aB = sbase + st * A_STG;
        const uint32_t bB = sbase + B_OFF + st * B_STG;

        #pragma unroll
        for (int kt = 0; kt < 2; kt++) {
            uint32_t af[MI][4], bf[4][4];
            #pragma unroll
            for (int mi = 0; mi < MI; mi++) {
                int rowb = wm * (MI * 16) + mi * 16 + (lane & 15);
                uint32_t addr = aB + rowb * 80 + kt * 32 + ((lane >> 4) << 4);
                ldsm4(af[mi], addr);
            }
            if (BNRELU) {
                const int pidx = kOff / 2 + it * 16 + kt * 8 + tg;
                __half2 s0 = hs[pidx],     o0 = hb[pidx];
                __half2 s1 = hs[pidx + 4], o1 = hb[pidx + 4];
                #pragma unroll
                for (int mi = 0; mi < MI; mi++) {
                    af[mi][0] = bnrelu2(af[mi][0], s0, o0);
                    af[mi][1] = bnrelu2(af[mi][1], s0, o0);
                    af[mi][2] = bnrelu2(af[mi][2], s1, o1);
                    af[mi][3] = bnrelu2(af[mi][3], s1, o1);
                }
            }
            #pragma unroll
            for (int jp = 0; jp < 4; jp++) {
                int rown = wn * 64 + jp * 16 + (lane & 7) + ((lane >> 4) << 3);
                uint32_t addr = bB + rown * 80 + kt * 32 + (((lane >> 3) & 1) << 4);
                ldsm4(bf[jp], addr);
            }
            #pragma unroll
            for (int mi = 0; mi < MI; mi++)
                #pragma unroll
                for (int jp = 0; jp < 4; jp++) {
                    mma16816(acc[mi][jp * 2],     af[mi], bf[jp][0], bf[jp][1]);
                    mma16816(acc[mi][jp * 2 + 1], af[mi], bf[jp][2], bf[jp][3]);
                }
        }
    }

    if (STATS) {
        float sl[8][2] = {}, ql[8][2] = {};
        #pragma unroll
        for (int nj = 0; nj < 8; nj++)
            #pragma unroll
            for (int mi = 0; mi < MI; mi++) {
                float v0 = acc[mi][nj][0], v1 = acc[mi][nj][1];
                float v2 = acc[mi][nj][2], v3 = acc[mi][nj][3];
                sl[nj][0] += v0 + v2;  ql[nj][0] += v0 * v0 + v2 * v2;
                sl[nj][1] += v1 + v3;  ql[nj][1] += v1 * v1 + v3 * v3;
            }
        #pragma unroll
        for (int off = 4; off < 32; off <<= 1)
            #pragma unroll
            for (int nj = 0; nj < 8; nj++) {
                sl[nj][0] += __shfl_xor_sync(~0u, sl[nj][0], off);
                sl[nj][1] += __shfl_xor_sync(~0u, sl[nj][1], off);
                ql[nj][0] += __shfl_xor_sync(~0u, ql[nj][0], off);
                ql[nj][1] += __shfl_xor_sync(~0u, ql[nj][1], off);
            }
        __syncthreads();
        float* sred = reinterpret_cast<float*>(sm);
        if (lane < 4) {
            #pragma unroll
            for (int nj = 0; nj < 8; nj++) {
                int col = wn * 64 + nj * 8 + lane * 2;
                sred[wm * COLS + col]     = sl[nj][0];
                sred[wm * COLS + col + 1] = sl[nj][1];
                sred[WM * COLS + wm * COLS + col]     = ql[nj][0];
                sred[WM * COLS + wm * COLS + col + 1] = ql[nj][1];
            }
        }
        __syncthreads();
        if (tid < COLS) {
            float s = 0.f, q = 0.f;
            #pragma unroll
            for (int w = 0; w < WM; w++) {
                s += sred[w * COLS + tid];
                q += sred[WM * COLS + w * COLS + tid];
            }
            part_s[(size_t)blockIdx.y * Cols + col0 + tid] = s;
            part_q[(size_t)blockIdx.y * Cols + col0 + tid] = q;
        }
    }

    const size_t splitOff = (SPLIT > 1) ? (size_t)blockIdx.z * R * Cols : 0;
    #pragma unroll
    for (int mi = 0; mi < MI; mi++) {
        int rbase = row0 + wm * (MI * 16) + mi * 16 + (lane >> 2);
        #pragma unroll
        for (int nj = 0; nj < 8; nj++) {
            int c = col0 + wn * 64 + nj * 8 + (lane & 3) * 2;
            if (HOUT) {
                __half* Ch = (__half*)Cout;
                if (rbase < R)
                    *reinterpret_cast<__half2*>(&Ch[(size_t)rbase * Cols + c]) =
                        __floats2half2_rn(acc[mi][nj][0], acc[mi][nj][1]);
                if (rbase + 8 < R)
                    *reinterpret_cast<__half2*>(&Ch[(size_t)(rbase + 8) * Cols + c]) =
                        __floats2half2_rn(acc[mi][nj][2], acc[mi][nj][3]);
            } else {
                float* Cf = (float*)Cout + splitOff;
                if (rbase < R)
                    *reinterpret_cast<float2*>(&Cf[(size_t)rbase * Cols + c]) =
                        make_float2(acc[mi][nj][0], acc[mi][nj][1]);
                if (rbase + 8 < R)
                    *reinterpret_cast<float2*>(&Cf[(size_t)(rbase + 8) * Cols + c]) =
                        make_float2(acc[mi][nj][2], acc[mi][nj][3]);
            }
        }
    }
}

// ---------------- transpose (b,c,l)->(b,1+l,c) fp16 + pool partials ----------------
__global__ void transpose_kernel(const float* __restrict__ x) {
    __shared__ float t[32][33];
    __shared__ float ps[8][32];
    int b  = blockIdx.z;
    int c0 = blockIdx.y * 32;
    int l0 = blockIdx.x * 32;
    int tx = threadIdx.x, ty = threadIdx.y;
    #pragma unroll
    for (int i = 0; i < 32; i += 8) {
        int c = c0 + ty + i, l = l0 + tx;
        t[ty + i][tx] = (l < LL) ? x[((size_t)b * Cc + c) * LL + l] : 0.f;
    }
    __syncthreads();
    #pragma unroll
    for (int i = 0; i < 32; i += 8) {
        int l = l0 + ty + i, c = c0 + tx;
        if (l < LL)
            d_X1h[((size_t)b * L1 + 1 + l) * Cc + c] = __float2half_rn(t[tx][ty + i]);
    }
    float p = t[tx][ty * 4] + t[tx][ty * 4 + 1] + t[tx][ty * 4 + 2] + t[tx][ty * 4 + 3];
    ps[ty][tx] = p;
    __syncthreads();
    if (ty == 0) {
        float s = 0.f;
        #pragma unroll
        for (int i = 0; i < 8; i++) s += ps[i][tx];
        d_poolp[((size_t)b * Cc + c0 + tx) * 7 + blockIdx.x] = s;
    }
}

// ---------------- pool finalize: X1 row 0 ----------------
__global__ void pool_final() {
    int idx = blockIdx.x * 256 + threadIdx.x;
    int b = idx >> 11, c = idx & (Cc - 1);
    float s = 0.f;
    #pragma unroll
    for (int j = 0; j < 7; j++) s += d_poolp[(size_t)idx * 7 + j];
    d_X1h[((size_t)b * L1) * Cc + c] = __float2half_rn(s * (1.f / (float)LL));
}

// ---------------- fused fp32 -> fp16 weight copies ----------------
#define WCP_N0  (HID * Cc / 4)
#define WCP_N1  (OUTC * HID / 4)
#define WCP_TOT (2 * WCP_N0 + 2 * WCP_N1)
__global__ void half_copy4(const float* __restrict__ s0, __half* __restrict__ d0,
                           const float* __restrict__ s1, __half* __restrict__ d1,
                           const float* __restrict__ s2, __half* __restrict__ d2,
                           const float* __restrict__ s3, __half* __restrict__ d3) {
    int i = blockIdx.x * 256 + threadIdx.x;
    const float* src; __half* dst; int off;
    if (i < WCP_N0)                       { src = s0; dst = d0; off = i; }
    else if (i < WCP_N0 + WCP_N1)         { src = s1; dst = d1; off = i - WCP_N0; }
    else if (i < 2 * WCP_N0 + WCP_N1)     { src = s2; dst = d2; off = i - WCP_N0 - WCP_N1; }
    else if (i < WCP_TOT)                 { src = s3; dst = d3; off = i - 2 * WCP_N0 - WCP_N1; }
    else return;
    float4 v = reinterpret_cast<const float4*>(src)[off];
    reinterpret_cast<__half2*>(dst)[off * 2    ] = __floats2half2_rn(v.x, v.y);
    reinterpret_cast<__half2*>(dst)[off * 2 + 1] = __floats2half2_rn(v.z, v.w);
}

// ---------------- BN finalize (4 workers per channel, fixed-order combine) ----
__global__ void bn_final(const float* __restrict__ g, const float* __restrict__ bta,
                         float invN, int nch) {
    int tid = threadIdx.x;
    int cl = tid >> 2, w = tid & 3;
    int o = blockIdx.x * 64 + cl;
    float s = 0.f, q = 0.f;
    for (int ch = w; ch < nch; ch += 4) {
        s += d_part_s[(size_t)ch * HID + o];
        q += d_part_q[(size_t)ch * HID + o];
    }
    s += __shfl_down_sync(~0u, s, 2);
    q += __shfl_down_sync(~0u, q, 2);
    s += __shfl_down_sync(~0u, s, 1);
    q += __shfl_down_sync(~0u, q, 1);
    if (w == 0) {
        float mu  = s * invN;
        float var = q * invN - mu * mu;
        float sc  = g[o] * rsqrtf(var + 1e-5f);
        reinterpret_cast<__half*>(d_hs)[o] = __float2half_rn(sc);
        reinterpret_cast<__half*>(d_hb)[o] = __float2half_rn(bta[o] - mu * sc);
    }
}

// ---------------- feature L2 norm ----------------
__global__ void norm_kernel() {
    int bl = blockIdx.x;
    int b = bl / LL, l = bl % LL;
    float v = d_Z[((size_t)b * L1 + 1 + l) * OUTC + threadIdx.x];
    float s = v * v;
    #pragma unroll
    for (int o = 16; o; o >>= 1) s += __shfl_down_sync(~0u, s, o);
    __shared__ float w[8];
    if ((threadIdx.x & 31) == 0) w[threadIdx.x >> 5] = s;
    __syncthreads();
    if (threadIdx.x == 0) {
        float t = 0.f;
        #pragma unroll
        for (int i = 0; i < 8; i++) t += w[i];
        d_nrm[bl] = sqrtf(t);
    }
}

// ---------------- softmax: smem-staged, coalesced Z reads (+ z_g) -------------
// grid (Bb, 8): block handles batch b, 32 channels jg..jg+31.
__global__ __launch_bounds__(256)
void softmax_kernel(float* __restrict__ out) {
    __shared__ float zt[LL][33];
    const int b  = blockIdx.x;
    const int jg = blockIdx.y * 32;
    const int tid = threadIdx.x;
    const int warp = tid >> 5, lane = tid & 31;

    // z_g slice for these 32 channels
    if (tid < 32)
        out[OFF_ZG + b * OUTC + jg + tid] = d_Z[((size_t)b * L1) * OUTC + jg + tid];

    // coalesced load: lanes vary j (consecutive floats)
    for (int idx = tid; idx < LL * 32; idx += 256) {
        int l = idx >> 5, j = idx & 31;
        zt[l][j] = d_Z[((size_t)b * L1 + 1 + l) * OUTC + jg + j];
    }
    __syncthreads();

    // per-lane norms (reused for all 4 j's this warp handles)
    float ln[7];
    #pragma unroll
    for (int i = 0; i < 7; i++) {
        int l = lane + i * 32;
        ln[i] = (l < LL) ? fmaxf(d_nrm[b * LL + l], 1e-12f) : 1.f;
    }

    // each warp handles 4 channels
    #pragma unroll
    for (int jj = 0; jj < 4; jj++) {
        int j = warp * 4 + jj;
        float v[7];
        float mx = -INFINITY;
        #pragma unroll
        for (int i = 0; i < 7; i++) {
            int l = lane + i * 32;
            if (l < LL) {
                v[i] = zt[l][j] / ln[i];
                mx = fmaxf(mx, v[i]);
            } else v[i] = -INFINITY;
        }
        #pragma unroll
        for (int o = 16; o; o >>= 1) mx = fmaxf(mx, __shfl_xor_sync(~0u, mx, o));
        float s = 0.f;
        #pragma unroll
        for (int i = 0; i < 7; i++) { v[i] = expf(v[i] - mx); s += v[i]; }
        #pragma unroll
        for (int o = 16; o; o >>= 1) s += __shfl_xor_sync(~0u, s, o);
        float inv = 1.f / s;
        #pragma unroll
        for (int i = 0; i < 7; i++) {
            int l = lane + i * 32;
            if (l < LL) {
                float r = v[i] * inv;
                size_t idx = ((size_t)b * OUTC + jg + j) * LL + l;
                out[OFF_ATTN + idx] = r;
                out[OFF_RAW  + idx] = r;
            }
        }
    }
}

// ---------------- attention-value einsum (reads fp16 X1h) -> fp16 Vt ----------------
__global__ __launch_bounds__(256)
void attnval_kernel(const float* __restrict__ out) {
    const float* attn = out + OFF_ATTN;
    int h = blockIdx.x, b = blockIdx.y;
    __shared__ __half xs2[32][256];
    __shared__ float  as2[32][36];
    int tid = threadIdx.x;
    float acc[KH] = {};

    for (int l0 = 0; l0 < LL; l0 += 32) {
        int lmax = min(32, LL - l0);
        #pragma unroll
        for (int i = 0; i < 4; i++) {
            int task = tid + i * 256;
            int row = task >> 5, t = task & 31;
            if (l0 + row < LL) {
                const uint4* src = reinterpret_cast<const uint4*>(
                    d_X1h + ((size_t)b * L1 + 1 + l0 + row) * Cc + h * CH) + t;
                *(reinterpret_cast<uint4*>(&xs2[row][0]) + t) = *src;
            }
        }
        #pragma unroll
        for (int i = 0; i < 4; i++) {
            int k   = (tid >> 5) + i * 8;
            int col = tid & 31;
            float v = 0.f;
            if (l0 + col < LL)
                v = attn[(((size_t)b * NH + h) * KH + k) * LL + l0 + col];
            as2[col][k] = v;
        }
        __syncthreads();
        for (int l = 0; l < lmax; l++) {
            float xv = __half2float(xs2[l][tid]);
            #pragma unroll
            for (int k4 = 0; k4 < KH / 4; k4++) {
                float4 w = *reinterpret_cast<const float4*>(&as2[l][k4 * 4]);
                acc[k4 * 4 + 0] = fmaf(xv, w.x, acc[k4 * 4 + 0]);
                acc[k4 * 4 + 1] = fmaf(xv, w.y, acc[k4 * 4 + 1]);
                acc[k4 * 4 + 2] = fmaf(xv, w.z, acc[k4 * 4 + 2]);
                acc[k4 * 4 + 3] = fmaf(xv, w.w, acc[k4 * 4 + 3]);
            }
        }
        __syncthreads();
    }
    #pragma unroll
    for (int k = 0; k < KH; k++)
        d_Vth[((size_t)b * KH + k) * Cc + h * CH + tid] = __float2half_rn(acc[k]);
}

// ---------------- permute + split-K reduce: smem-staged, coalesced ------------
// grid (Bb, 8): block handles batch b, 32 output channels j0..j0+31, all 32 k.
__global__ __launch_bounds__(256)
void permute_kernel(float* __restrict__ out) {
    __shared__ float t[32][33];
    const int b  = blockIdx.x;
    const int j0 = blockIdx.y * 32;
    const int tid = threadIdx.x;

    // coalesced read: lanes vary j (consecutive floats within a P4 row)
    for (int idx = tid; idx < 32 * 32; idx += 256) {
        int k = idx >> 5, j = idx & 31;
        size_t src = ((size_t)b * KH + k) * OUTC + j0 + j;
        float s = 0.f;
        #pragma unroll
        for (int z = 0; z < 4; z++) s += d_P4[(size_t)z * N2 * OUTC + src];
        t[k][j] = s;
    }
    __syncthreads();

    // coalesced write: lanes vary k (consecutive floats in out)
    for (int idx = tid; idx < 32 * 32; idx += 256) {
        int j = idx >> 5, k = idx & 31;
        out[OFF_VAL + ((size_t)b * OUTC + j0 + j) * KH + k] = t[k][j];
    }
}

// ---------------- launch ----------------
extern "C" void kernel_launch(void* const* d_in, const int* in_sizes, int n_in,
                              void* d_out, int out_size) {
    const float* x    = (const float*)d_in[0];
    const float* w1_p = (const float*)d_in[1];
    const float* g_p  = (const float*)d_in[2];
    const float* b_p  = (const float*)d_in[3];
    const float* w2_p = (const float*)d_in[4];
    const float* w1_o = (const float*)d_in[5];
    const float* g_o  = (const float*)d_in[6];
    const float* b_o  = (const float*)d_in[7];
    const float* w2_o = (const float*)d_in[8];
    float* out = (float*)d_out;

    float *pZ, *pP4, *pPs, *pPq;
    __half *pX1h, *pHh, *pVth, *pW1p, *pW2p, *pW1o, *pW2o;
    __half2 *pHs, *pHb;
    cudaGetSymbolAddress((void**)&pX1h, d_X1h);
    cudaGetSymbolAddress((void**)&pHh,  d_Hh);
    cudaGetSymbolAddress((void**)&pZ,   d_Z);
    cudaGetSymbolAddress((void**)&pVth, d_Vth);
    cudaGetSymbolAddress((void**)&pP4,  d_P4);
    cudaGetSymbolAddress((void**)&pPs,  d_part_s);
    cudaGetSymbolAddress((void**)&pPq,  d_part_q);
    cudaGetSymbolAddress((void**)&pHs,  d_hs);
    cudaGetSymbolAddress((void**)&pHb,  d_hb);
    cudaGetSymbolAddress((void**)&pW1p, d_W1p);
    cudaGetSymbolAddress((void**)&pW2p, d_W2p);
    cudaGetSymbolAddress((void**)&pW1o, d_W1o);
    cudaGetSymbolAddress((void**)&pW2o, d_W2o);

    auto gemm1  = gemm_h<128, 128, true,  false, true,  1>;  // GEMM1/3: fp16 H + stats
    auto gemm2  = gemm_h<128, 128, false, true,  false, 1>;  // GEMM2: BN+ReLU fused A
    auto gemm4  = gemm_h<64,  128, false, true,  false, 4>;  // GEMM4: BN+ReLU, split-K4
    constexpr int SM_128 = 4 * (128 * 80 + 128 * 80);   // 81920
    constexpr int SM_64  = 4 * (64  * 80 + 128 * 80);   // 61440
    cudaFuncSetAttribute(gemm1, cudaFuncAttributeMaxDynamicSharedMemorySize, SM_128);
    cudaFuncSetAttribute(gemm2, cudaFuncAttributeMaxDynamicSharedMemorySize, SM_128);
    cudaFuncSetAttribute(gemm4, cudaFuncAttributeMaxDynamicSharedMemorySize, SM_64);

    // weights -> fp16 (single fused launch)
    half_copy4<<<(WCP_TOT + 255) / 256, 256>>>(w1_p, pW1p, w2_p, pW2p,
                                               w1_o, pW1o, w2_o, pW2o);

    // 0) transpose + pool partials, then pool finalize (X1 row 0)
    transpose_kernel<<<dim3(7, Cc / 32, Bb), dim3(32, 8)>>>(x);
    pool_final<<<(Bb * Cc) / 256, 256>>>();

    // 1) H = X1 @ w1_p^T (12608 x 2048 x 2048), fp16 out + fused BN stats
    gemm1<<<dim3(HID / 128, (N1 + 127) / 128), 256, SM_128>>>(
        pX1h, pW1p, pHh, N1, HID, nullptr, nullptr, pPs, pPq);

    // 2) BN finalize (4 workers/channel)
    bn_final<<<HID / 64, 256>>>(g_p, b_p, 1.f / (float)N1, (N1 + 127) / 128);

    // 3) Z = relu(bn(H)) @ w2_p^T, BN+ReLU fused into A fragments
    gemm2<<<dim3(OUTC / 128, (N1 + 127) / 128), 256, SM_128>>>(
        pHh, pW2p, pZ, N1, OUTC, pHs, pHb, nullptr, nullptr);

    // 4) norms; coalesced softmax (+ fused z_g)
    norm_kernel<<<Bb * LL, 256>>>();
    softmax_kernel<<<dim3(Bb, 8), 256>>>(out);

    // 5) attention value (fp16 X1h input) -> fp16 Vt
    attnval_kernel<<<dim3(NH, Bb), 256>>>(out);

    // 6) H = Vt @ w1_o^T (2048 x 2048 x 2048), fp16 out + fused BN stats
    gemm1<<<dim3(HID / 128, N2 / 128), 256, SM_128>>>(
        pVth, pW1o, pHh, N2, HID, nullptr, nullptr, pPs, pPq);

    // 7) BN finalize 2
    bn_final<<<HID / 64, 256>>>(g_o, b_o, 1.f / (float)N2, N2 / 128);

    // 8) C4 partials = relu(bn(H)) @ w2_o^T, split-K x4 -> 256 CTAs
    gemm4<<<dim3(OUTC / 128, N2 / 64, 4), 256, SM_64>>>(
        pHh, pW2o, pP4, N2, OUTC, pHs, pHb, nullptr, nullptr);

    // 9) permute + split-K reduce to obj_val layout (coalesced both sides)
    permute_kernel<<<dim3(Bb, 8), 256>>>(out);
}